// round 3
// baseline (speedup 1.0000x reference)
#include <cuda_runtime.h>
#include <math.h>

#define SEQ   2048
#define BATCH 2
#define NH    16
#define DKV   64
#define DM    1024
#define MTOT  (BATCH*SEQ)

// Scratch (allocation-free: static device globals)
__device__ __align__(16) float g_q[BATCH*NH*SEQ*DKV];
__device__ __align__(16) float g_k[BATCH*NH*SEQ*DKV];
__device__ __align__(16) float g_v[BATCH*NH*SEQ*DKV];
__device__ __align__(16) float g_ctx[MTOT*DM];

// ---------------------------------------------------------------------------
// Classic 128x128x8 SGEMM, 256 threads, 8x8 microtile per thread.
// mode 0: C row-major [M,N].  mode 1: scatter to head-major [B,H,S,Dk].
// ---------------------------------------------------------------------------
__global__ __launch_bounds__(256) void sgemm_kernel(
    const float* __restrict__ A, const float* __restrict__ B,
    float* __restrict__ C, int M, int N, int K, int mode)
{
    __shared__ float As[8][128];
    __shared__ float Bs[8][128];
    const int tid  = threadIdx.x;
    const int row0 = blockIdx.y * 128;
    const int col0 = blockIdx.x * 128;
    const int aRow = tid >> 1, aCol = (tid & 1) * 4;
    const int bRow = tid >> 5, bCol = (tid & 31) * 4;
    const int ty = tid >> 4, tx = tid & 15;

    float acc[8][8];
    #pragma unroll
    for (int i = 0; i < 8; i++)
        #pragma unroll
        for (int j = 0; j < 8; j++) acc[i][j] = 0.f;

    const float* Aptr = A + (size_t)(row0 + aRow) * K + aCol;
    const float* Bptr = B + (size_t)bRow * N + col0 + bCol;

    for (int k0 = 0; k0 < K; k0 += 8) {
        float4 av = *(const float4*)(Aptr + k0);
        float4 bv = *(const float4*)(Bptr + (size_t)k0 * N);
        As[aCol+0][aRow] = av.x;
        As[aCol+1][aRow] = av.y;
        As[aCol+2][aRow] = av.z;
        As[aCol+3][aRow] = av.w;
        *(float4*)&Bs[bRow][bCol] = bv;
        __syncthreads();
        #pragma unroll
        for (int kk = 0; kk < 8; kk++) {
            float ra[8], rb[8];
            #pragma unroll
            for (int i = 0; i < 8; i++) ra[i] = As[kk][ty*8+i];
            #pragma unroll
            for (int j = 0; j < 8; j++) rb[j] = Bs[kk][tx*8+j];
            #pragma unroll
            for (int i = 0; i < 8; i++)
                #pragma unroll
                for (int j = 0; j < 8; j++)
                    acc[i][j] = fmaf(ra[i], rb[j], acc[i][j]);
        }
        __syncthreads();
    }

    if (mode == 0) {
        #pragma unroll
        for (int i = 0; i < 8; i++) {
            int r = row0 + ty*8 + i;
            float* cp = C + (size_t)r * N + col0 + tx*8;
            *(float4*)cp       = make_float4(acc[i][0], acc[i][1], acc[i][2], acc[i][3]);
            *(float4*)(cp + 4) = make_float4(acc[i][4], acc[i][5], acc[i][6], acc[i][7]);
        }
    } else {
        // head-major scatter: row r = b*SEQ+s, col c = h*DKV+d
        int c0 = col0 + tx*8;
        int hh = c0 >> 6, dd = c0 & 63;
        #pragma unroll
        for (int i = 0; i < 8; i++) {
            int r  = row0 + ty*8 + i;
            int bb = r >> 11, ss = r & (SEQ-1);
            float* cp = C + (((size_t)(bb*NH + hh) * SEQ) + ss) * DKV + dd;
            *(float4*)cp       = make_float4(acc[i][0], acc[i][1], acc[i][2], acc[i][3]);
            *(float4*)(cp + 4) = make_float4(acc[i][4], acc[i][5], acc[i][6], acc[i][7]);
        }
    }
}

// ---------------------------------------------------------------------------
// Flash attention with T5 relative-position bias.
// Grid: (SEQ/64, NH, BATCH), 256 threads (8 warps x 8 q-rows each).
// ---------------------------------------------------------------------------
#define ATTN_SMEM_FLOATS (4096 + 2112 + 2048 + 2048 + 2112 + 32)
#define ATTN_SMEM_BYTES  (ATTN_SMEM_FLOATS * 4)

__global__ __launch_bounds__(256) void attn_kernel(const float* __restrict__ rel_emb)
{
    extern __shared__ float sm[];
    float* Qs    = sm;            // [64][64]
    float* Kts   = sm + 4096;     // [64][33]  (K transposed, padded)
    float* Vs    = sm + 6208;     // [32][64]
    float* Ps    = sm + 8256;     // [8 warps][8 rows][32]
    float* biasS = sm + 10304;    // [2111] bias values for this (q0, h)
    float* embh  = sm + 12416;    // [32] rel_emb column for head h

    const int tid = threadIdx.x;
    const int b  = blockIdx.z, h = blockIdx.y;
    const int q0 = blockIdx.x * 64;

    const float* Qp = g_q + (((size_t)b*NH + h)*SEQ + q0) * DKV;
    const float* Kp = g_k + ((size_t)b*NH + h)*SEQ*DKV;
    const float* Vp = g_v + ((size_t)b*NH + h)*SEQ*DKV;

    #pragma unroll
    for (int i = 0; i < 4; i++) {
        int idx = (tid + i*256) * 4;
        *(float4*)&Qs[idx] = *(const float4*)&Qp[idx];
    }
    if (tid < 32) embh[tid] = rel_emb[tid*NH + h];
    __syncthreads();

    // Inline T5 bidirectional bucket -> bias slice for rel = k - q in
    // [-(q0+63), 2047-q0], index j = rel + q0 + 63.
    for (int j = tid; j < 2111; j += 256) {
        int rel = j - (q0 + 63);     // mem - ctx
        int n = -rel;                // ctx - mem
        int ret = 0;
        if (n < 0) { ret = 16; n = -n; }
        int bkt;
        if (n < 8) bkt = n;
        else {
            float t = logf((float)n * 0.125f);
            t = t / 2.7725887222397812f;   // f32(log(16)); == 4*f32(log 2) bit-exact
            t = t * 8.0f;
            int v = 8 + (int)t;
            bkt = v < 15 ? v : 15;
        }
        biasS[j] = embh[ret + bkt];
    }

    const int w = tid >> 5, lane = tid & 31;
    const int r0 = w * 8;
    float m[8], l[8], a0[8], a1[8];
    #pragma unroll
    for (int r = 0; r < 8; r++) { m[r] = -3.0e38f; l[r] = 0.f; a0[r] = 0.f; a1[r] = 0.f; }

    const int kRow = tid >> 3;
    const int cc   = (tid & 7) * 8;

    for (int kv0 = 0; kv0 < SEQ; kv0 += 32) {
        __syncthreads();   // previous tile compute done (and bias ready on iter 0)
        {
            const float* kp = Kp + (size_t)(kv0 + kRow)*DKV + cc;
            float4 ka = *(const float4*)kp;
            float4 kb = *(const float4*)(kp + 4);
            Kts[(cc+0)*33 + kRow] = ka.x;
            Kts[(cc+1)*33 + kRow] = ka.y;
            Kts[(cc+2)*33 + kRow] = ka.z;
            Kts[(cc+3)*33 + kRow] = ka.w;
            Kts[(cc+4)*33 + kRow] = kb.x;
            Kts[(cc+5)*33 + kRow] = kb.y;
            Kts[(cc+6)*33 + kRow] = kb.z;
            Kts[(cc+7)*33 + kRow] = kb.w;
            const float* vp = Vp + (size_t)(kv0 + kRow)*DKV + cc;
            *(float4*)&Vs[kRow*DKV + cc]     = *(const float4*)vp;
            *(float4*)&Vs[kRow*DKV + cc + 4] = *(const float4*)(vp + 4);
        }
        __syncthreads();

        // scores: each lane owns kv column (kv0+lane), 8 q-rows
        float sc[8];
        #pragma unroll
        for (int r = 0; r < 8; r++) sc[r] = 0.f;
        #pragma unroll 4
        for (int d4 = 0; d4 < 64; d4 += 4) {
            float k0v = Kts[(d4+0)*33 + lane];
            float k1v = Kts[(d4+1)*33 + lane];
            float k2v = Kts[(d4+2)*33 + lane];
            float k3v = Kts[(d4+3)*33 + lane];
            #pragma unroll
            for (int r = 0; r < 8; r++) {
                float4 qv = *(const float4*)&Qs[(r0+r)*64 + d4];
                sc[r] = fmaf(qv.x, k0v, sc[r]);
                sc[r] = fmaf(qv.y, k1v, sc[r]);
                sc[r] = fmaf(qv.z, k2v, sc[r]);
                sc[r] = fmaf(qv.w, k3v, sc[r]);
            }
        }

        // bias + online softmax update
        #pragma unroll
        for (int r = 0; r < 8; r++) {
            float s = sc[r] + biasS[kv0 + lane - r0 - r + 63];
            float tm = s;
            #pragma unroll
            for (int o = 16; o; o >>= 1)
                tm = fmaxf(tm, __shfl_xor_sync(0xffffffffu, tm, o));
            float mnew = fmaxf(m[r], tm);
            float p    = exp2f((s    - mnew) * 1.44269504f);
            float corr = exp2f((m[r] - mnew) * 1.44269504f);
            float ts = p;
            #pragma unroll
            for (int o = 16; o; o >>= 1)
                ts += __shfl_xor_sync(0xffffffffu, ts, o);
            l[r] = l[r]*corr + ts;
            m[r] = mnew;
            a0[r] *= corr; a1[r] *= corr;
            Ps[(r0 + r)*32 + lane] = p;
        }
        __syncwarp();

        // accumulate P @ V (lane owns output dims lane and lane+32)
        #pragma unroll 2
        for (int k4 = 0; k4 < 32; k4 += 4) {
            float v00 = Vs[(k4+0)*64 + lane], v01 = Vs[(k4+0)*64 + 32 + lane];
            float v10 = Vs[(k4+1)*64 + lane], v11 = Vs[(k4+1)*64 + 32 + lane];
            float v20 = Vs[(k4+2)*64 + lane], v21 = Vs[(k4+2)*64 + 32 + lane];
            float v30 = Vs[(k4+3)*64 + lane], v31 = Vs[(k4+3)*64 + 32 + lane];
            #pragma unroll
            for (int r = 0; r < 8; r++) {
                float4 pv = *(const float4*)&Ps[(r0+r)*32 + k4];
                a0[r] = fmaf(pv.x, v00, a0[r]); a1[r] = fmaf(pv.x, v01, a1[r]);
                a0[r] = fmaf(pv.y, v10, a0[r]); a1[r] = fmaf(pv.y, v11, a1[r]);
                a0[r] = fmaf(pv.z, v20, a0[r]); a1[r] = fmaf(pv.z, v21, a1[r]);
                a0[r] = fmaf(pv.w, v30, a0[r]); a1[r] = fmaf(pv.w, v31, a1[r]);
            }
        }
        __syncwarp();
    }

    // epilogue: ctx[b, q, h*64 + d]
    #pragma unroll
    for (int r = 0; r < 8; r++) {
        float inv = 1.0f / l[r];
        int q = q0 + r0 + r;
        float* op = g_ctx + ((size_t)(b*SEQ + q))*DM + h*DKV;
        op[lane]      = a0[r] * inv;
        op[lane + 32] = a1[r] * inv;
    }
}

// ---------------------------------------------------------------------------
extern "C" void kernel_launch(void* const* d_in, const int* in_sizes, int n_in,
                              void* d_out, int out_size)
{
    const float* x   = (const float*)d_in[0];
    const float* wq  = (const float*)d_in[1];
    const float* wk  = (const float*)d_in[2];
    const float* wv  = (const float*)d_in[3];
    const float* wo  = (const float*)d_in[4];
    const float* rel = (const float*)d_in[5];
    float* out = (float*)d_out;

    float *dq, *dk, *dv, *dctx;
    cudaGetSymbolAddress((void**)&dq,   g_q);
    cudaGetSymbolAddress((void**)&dk,   g_k);
    cudaGetSymbolAddress((void**)&dv,   g_v);
    cudaGetSymbolAddress((void**)&dctx, g_ctx);

    cudaFuncSetAttribute(attn_kernel,
                         cudaFuncAttributeMaxDynamicSharedMemorySize,
                         ATTN_SMEM_BYTES);

    dim3 gg(DM/128, MTOT/128), bb(256);
    sgemm_kernel<<<gg, bb>>>(x, wq, dq, MTOT, DM, DM, 1);
    sgemm_kernel<<<gg, bb>>>(x, wk, dk, MTOT, DM, DM, 1);
    sgemm_kernel<<<gg, bb>>>(x, wv, dv, MTOT, DM, DM, 1);
    attn_kernel<<<dim3(SEQ/64, NH, BATCH), 256, ATTN_SMEM_BYTES>>>(rel);
    sgemm_kernel<<<gg, bb>>>(dctx, wo, out, MTOT, DM, DM, 0);
}

// round 5
// speedup vs baseline: 2.5121x; 2.5121x over previous
#include <cuda_runtime.h>
#include <cuda_fp16.h>
#include <stdint.h>
#include <math.h>

#define SEQ   2048
#define BATCH 2
#define NH    16
#define DKV   64
#define DM    1024
#define MTOT  (BATCH*SEQ)
#define LOG2E 1.44269504f

// ---- static device scratch (no allocs) ----
__device__ __align__(16) __half g_xh[MTOT*DM], g_xl[MTOT*DM];
__device__ __align__(16) __half g_wth[4][DM*DM], g_wtl[4][DM*DM];
__device__ __align__(16) __half g_qh[BATCH*NH*SEQ*DKV], g_ql[BATCH*NH*SEQ*DKV];
__device__ __align__(16) __half g_kh[BATCH*NH*SEQ*DKV], g_kl[BATCH*NH*SEQ*DKV];
__device__ __align__(16) __half g_vh[BATCH*NH*SEQ*DKV];
__device__ __align__(16) __half g_ch[MTOT*DM], g_cl[MTOT*DM];

// ---- helpers ----
__device__ __forceinline__ uint32_t smem_u32(const void* p) {
    uint32_t a;
    asm("{ .reg .u64 t; cvta.to.shared.u64 t, %1; cvt.u32.u64 %0, t; }" : "=r"(a) : "l"(p));
    return a;
}
__device__ __forceinline__ void hmma(float* d, const uint32_t* a, uint32_t b0, uint32_t b1) {
    asm volatile("mma.sync.aligned.m16n8k16.row.col.f32.f16.f16.f32 "
        "{%0,%1,%2,%3}, {%4,%5,%6,%7}, {%8,%9}, {%0,%1,%2,%3};"
        : "+f"(d[0]), "+f"(d[1]), "+f"(d[2]), "+f"(d[3])
        : "r"(a[0]), "r"(a[1]), "r"(a[2]), "r"(a[3]), "r"(b0), "r"(b1));
}
__device__ __forceinline__ void ldsm4(uint32_t* r, uint32_t addr) {
    asm volatile("ldmatrix.sync.aligned.m8n8.x4.shared.b16 {%0,%1,%2,%3}, [%4];"
        : "=r"(r[0]), "=r"(r[1]), "=r"(r[2]), "=r"(r[3]) : "r"(addr));
}
__device__ __forceinline__ void ldsm4t(uint32_t* r, uint32_t addr) {
    asm volatile("ldmatrix.sync.aligned.m8n8.x4.trans.shared.b16 {%0,%1,%2,%3}, [%4];"
        : "=r"(r[0]), "=r"(r[1]), "=r"(r[2]), "=r"(r[3]) : "r"(addr));
}
__device__ __forceinline__ void cpa(uint32_t dst, const void* src) {
    asm volatile("cp.async.cg.shared.global [%0], [%1], 16;" :: "r"(dst), "l"(src));
}
#define CP_COMMIT() asm volatile("cp.async.commit_group;" ::: "memory")
#define CP_WAIT1()  asm volatile("cp.async.wait_group 1;" ::: "memory")
#define CP_WAIT0()  asm volatile("cp.async.wait_group 0;" ::: "memory")

__device__ __forceinline__ void split2(float v, __half& hi, __half& lo) {
    hi = __float2half_rn(v);
    lo = __float2half_rn(v - __half2float(hi));
}
__device__ __forceinline__ uint32_t packh2(float a, float b) {
    __half2 h = __floats2half2_rn(a, b);
    return *(uint32_t*)&h;
}

// ---- prep ----
__global__ __launch_bounds__(256) void split_x_kernel(const float* __restrict__ x) {
    int i = (blockIdx.x * 256 + threadIdx.x) * 4;
    float4 v = *(const float4*)(x + i);
    __half h0,h1,h2,h3,l0,l1,l2,l3;
    split2(v.x,h0,l0); split2(v.y,h1,l1); split2(v.z,h2,l2); split2(v.w,h3,l3);
    __half2 hh[2] = { __halves2half2(h0,h1), __halves2half2(h2,h3) };
    __half2 ll[2] = { __halves2half2(l0,l1), __halves2half2(l2,l3) };
    *(uint2*)(g_xh + i) = *(uint2*)hh;
    *(uint2*)(g_xl + i) = *(uint2*)ll;
}
__global__ __launch_bounds__(256) void wsplitT_kernel(const float* __restrict__ W,
                                                      __half* __restrict__ Th, __half* __restrict__ Tl) {
    __shared__ float t[32][33];
    int n0 = blockIdx.x * 32, k0 = blockIdx.y * 32;
    int tx = threadIdx.x, ty = threadIdx.y;
    #pragma unroll
    for (int i = 0; i < 32; i += 8)
        t[ty + i][tx] = W[(size_t)(k0 + ty + i) * DM + n0 + tx];
    __syncthreads();
    #pragma unroll
    for (int i = 0; i < 32; i += 8) {
        int n = n0 + ty + i, k = k0 + tx;
        __half hi, lo; split2(t[tx][ty + i], hi, lo);
        Th[(size_t)n * DM + k] = hi;
        Tl[(size_t)n * DM + k] = lo;
    }
}

// ---- split-fp16 MMA GEMM: C[M,N] = A[M,K]*W[K,N]; B = W^T rows [N][K] ----
// mode 0: fp32 row-major. mode 1: hi/lo fp16 head-major. mode 2: hi only head-major.
#define G_SMEM 131072

__device__ __forceinline__ void gemm_issue(uint32_t smb, const __half* const* mats,
                                           int c, int buf, int tid) {
    #pragma unroll
    for (int t = 0; t < 16; t++) {
        int u = tid + t * 256;
        int mat = u >> 10, rem = u & 1023, row = rem >> 3, seg = rem & 7;
        const void* src = mats[mat] + (size_t)row * DM + c * 64 + seg * 8;
        uint32_t dst = smb + buf * 65536 + mat * 16384 + row * 128 + ((seg ^ (row & 7)) << 4);
        cpa(dst, src);
    }
    CP_COMMIT();
}

__global__ __launch_bounds__(256) void gemm_mma(
    const __half* __restrict__ Ah, const __half* __restrict__ Al,
    const __half* __restrict__ Bh, const __half* __restrict__ Bl,
    float* __restrict__ Cf, __half* __restrict__ Oh, __half* __restrict__ Ol, int mode)
{
    extern __shared__ char smg[];
    uint32_t smb = smem_u32(smg);
    const int tid = threadIdx.x, lane = tid & 31, wid = tid >> 5;
    const int m0 = blockIdx.y * 128, n0 = blockIdx.x * 128;
    const int wm = wid >> 1, wn = wid & 1;

    const __half* mats[4] = { Ah + (size_t)m0 * DM, Al + (size_t)m0 * DM,
                              Bh + (size_t)n0 * DM, Bl + (size_t)n0 * DM };

    float acc[2][8][4];
    #pragma unroll
    for (int i = 0; i < 2; i++)
        #pragma unroll
        for (int j = 0; j < 8; j++)
            #pragma unroll
            for (int e = 0; e < 4; e++) acc[i][j][e] = 0.f;

    const int rsel = (lane & 7) + ((lane >> 3) & 1) * 8;
    const int chalf = lane >> 4;

    gemm_issue(smb, mats, 0, 0, tid);
    for (int c = 0; c < 16; c++) {
        if (c < 15) { gemm_issue(smb, mats, c + 1, (c + 1) & 1, tid); CP_WAIT1(); }
        else CP_WAIT0();
        __syncthreads();
        uint32_t ab = smb + (c & 1) * 65536;
        #pragma unroll
        for (int ks = 0; ks < 4; ks++) {
            uint32_t ah[2][4], al_[2][4], bh_[4][4], bl_[4][4];
            int sseg = 2 * ks + chalf;
            #pragma unroll
            for (int mi = 0; mi < 2; mi++) {
                int row = wm * 32 + mi * 16 + rsel;
                uint32_t off = row * 128 + ((sseg ^ (row & 7)) << 4);
                ldsm4(ah[mi], ab + off);
                ldsm4(al_[mi], ab + 16384 + off);
            }
            #pragma unroll
            for (int njp = 0; njp < 4; njp++) {
                int row = wn * 64 + njp * 16 + rsel;
                uint32_t off = row * 128 + ((sseg ^ (row & 7)) << 4);
                ldsm4(bh_[njp], ab + 32768 + off);
                ldsm4(bl_[njp], ab + 49152 + off);
            }
            #pragma unroll
            for (int mi = 0; mi < 2; mi++)
                #pragma unroll
                for (int njp = 0; njp < 4; njp++) {
                    hmma(acc[mi][2*njp],   ah[mi],  bh_[njp][0], bh_[njp][2]);
                    hmma(acc[mi][2*njp+1], ah[mi],  bh_[njp][1], bh_[njp][3]);
                    hmma(acc[mi][2*njp],   ah[mi],  bl_[njp][0], bl_[njp][2]);
                    hmma(acc[mi][2*njp+1], ah[mi],  bl_[njp][1], bl_[njp][3]);
                    hmma(acc[mi][2*njp],   al_[mi], bh_[njp][0], bh_[njp][2]);
                    hmma(acc[mi][2*njp+1], al_[mi], bh_[njp][1], bh_[njp][3]);
                }
        }
        __syncthreads();
    }

    const int g = lane >> 2, q2 = (lane & 3) * 2;
    #pragma unroll
    for (int mi = 0; mi < 2; mi++)
        #pragma unroll
        for (int rr = 0; rr < 2; rr++) {
            int m = m0 + wm * 32 + mi * 16 + g + rr * 8;
            #pragma unroll
            for (int nj = 0; nj < 8; nj++) {
                float v0 = acc[mi][nj][rr * 2], v1 = acc[mi][nj][rr * 2 + 1];
                int n = n0 + wn * 64 + nj * 8 + q2;
                if (mode == 0) {
                    *(float2*)(Cf + (size_t)m * DM + n) = make_float2(v0, v1);
                } else {
                    int bb = m >> 11, ss = m & (SEQ - 1), hh = n >> 6, dd = n & 63;
                    size_t off = (((size_t)(bb * NH + hh)) * SEQ + ss) * DKV + dd;
                    __half h0, h1, l0, l1;
                    split2(v0, h0, l0); split2(v1, h1, l1);
                    __half2 ph = __halves2half2(h0, h1);
                    *(uint32_t*)(Oh + off) = *(uint32_t*)&ph;
                    if (mode == 1) {
                        __half2 pl = __halves2half2(l0, l1);
                        *(uint32_t*)(Ol + off) = *(uint32_t*)&pl;
                    }
                }
            }
        }
}

// ---- FA2-style mma.sync flash attention ----
#define AT_QH 0
#define AT_QL 16384
#define AT_KV 32768            /* 2 bufs x 24576 (Kh 8K | Kl 8K | V 8K) */
#define AT_BI 81920
#define AT_SMEM (81920 + 2176*4)

__device__ __forceinline__ void attn_issue(uint32_t smb, const __half* kh, const __half* kl,
                                           const __half* vh, int t, int buf, int tid) {
    #pragma unroll
    for (int i = 0; i < 6; i++) {
        int u = tid + i * 256;
        int mat = u >> 9, rem = u & 511, row = rem >> 3, seg = rem & 7;
        const __half* base = (mat == 0) ? kh : (mat == 1) ? kl : vh;
        const void* src = base + (size_t)(t * 64 + row) * DKV + seg * 8;
        uint32_t dst = smb + AT_KV + buf * 24576 + mat * 8192 + row * 128 + ((seg ^ (row & 7)) << 4);
        cpa(dst, src);
    }
    CP_COMMIT();
}

__global__ __launch_bounds__(256) void attn_mma(const float* __restrict__ rel_emb)
{
    extern __shared__ char smn[];
    uint32_t smb = smem_u32(smn);
    const int tid = threadIdx.x, lane = tid & 31, wid = tid >> 5;
    const int b = blockIdx.z, h = blockIdx.y, q0 = blockIdx.x * 128;
    const size_t hoff = ((size_t)(b * NH + h)) * SEQ * DKV;
    const __half* kh = g_kh + hoff;
    const __half* kl = g_kl + hoff;
    const __half* vh = g_vh + hoff;

    attn_issue(smb, kh, kl, vh, 0, 0, tid);

    // Q staging (hi/lo), swizzled
    #pragma unroll
    for (int i = 0; i < 8; i++) {
        int u = tid + i * 256;
        int mat = u >> 10, rem = u & 1023, row = rem >> 3, seg = rem & 7;
        const uint4* src = (const uint4*)(((mat == 0) ? g_qh : g_ql) + hoff
                             + (size_t)(q0 + row) * DKV + seg * 8);
        *(uint4*)(smn + mat * 16384 + row * 128 + ((seg ^ (row & 7)) << 4)) = *src;
    }
    // bias table (exact reference bucket math)
    float* biasS = (float*)(smn + AT_BI);
    for (int j = tid; j < 2175; j += 256) {
        int rel = j - (q0 + 127);
        int n = -rel, ret = 0;
        if (n < 0) { ret = 16; n = -n; }
        int bkt;
        if (n < 8) bkt = n;
        else {
            float t = logf((float)n * 0.125f) / 2.7725887222397812f * 8.0f;
            int v = 8 + (int)t;
            bkt = v < 15 ? v : 15;
        }
        biasS[j] = __ldg(&rel_emb[(ret + bkt) * NH + h]);
    }
    __syncthreads();

    // Q fragments (resident)
    const int rsel = (lane & 7) + ((lane >> 3) & 1) * 8;
    const int chalf = lane >> 4;
    uint32_t qfh[4][4], qfl[4][4];
    {
        int qrow = wid * 16 + rsel;
        #pragma unroll
        for (int ks = 0; ks < 4; ks++) {
            int seg = 2 * ks + chalf;
            uint32_t off = qrow * 128 + ((seg ^ (qrow & 7)) << 4);
            ldsm4(qfh[ks], smb + AT_QH + off);
            ldsm4(qfl[ks], smb + AT_QL + off);
        }
    }

    float O[8][4];
    #pragma unroll
    for (int j = 0; j < 8; j++)
        #pragma unroll
        for (int e = 0; e < 4; e++) O[j][e] = 0.f;
    float m0r = -1e30f, m1r = -1e30f, l0 = 0.f, l1 = 0.f;
    const int g = lane >> 2, q2 = (lane & 3) * 2;
    const int qr0 = wid * 16 + g;

    for (int t = 0; t < 32; t++) {
        if (t < 31) { attn_issue(smb, kh, kl, vh, t + 1, (t + 1) & 1, tid); CP_WAIT1(); }
        else CP_WAIT0();
        __syncthreads();
        uint32_t kb = smb + AT_KV + (t & 1) * 24576;

        float s[8][4];
        #pragma unroll
        for (int j = 0; j < 8; j++)
            #pragma unroll
            for (int e = 0; e < 4; e++) s[j][e] = 0.f;

        #pragma unroll
        for (int ks = 0; ks < 4; ks++) {
            uint32_t kbh[4][4], kbl[4][4];
            int sseg = 2 * ks + chalf;
            #pragma unroll
            for (int njp = 0; njp < 4; njp++) {
                int row = njp * 16 + rsel;
                uint32_t off = row * 128 + ((sseg ^ (row & 7)) << 4);
                ldsm4(kbh[njp], kb + off);
                ldsm4(kbl[njp], kb + 8192 + off);
            }
            #pragma unroll
            for (int njp = 0; njp < 4; njp++) {
                hmma(s[2*njp],   qfh[ks], kbh[njp][0], kbh[njp][2]);
                hmma(s[2*njp+1], qfh[ks], kbh[njp][1], kbh[njp][3]);
                hmma(s[2*njp],   qfh[ks], kbl[njp][0], kbl[njp][2]);
                hmma(s[2*njp+1], qfh[ks], kbl[njp][1], kbl[njp][3]);
                hmma(s[2*njp],   qfl[ks], kbh[njp][0], kbh[njp][2]);
                hmma(s[2*njp+1], qfl[ks], kbh[njp][1], kbh[njp][3]);
            }
        }

        // bias + in-register online softmax (rows g, g+8 within warp tile)
        const float* bp0 = biasS + t * 64 + q2 + 127 - qr0;
        const float* bp1 = bp0 - 8;
        float mx0 = m0r, mx1 = m1r;
        #pragma unroll
        for (int nj = 0; nj < 8; nj++) {
            s[nj][0] += bp0[nj * 8];     s[nj][1] += bp0[nj * 8 + 1];
            s[nj][2] += bp1[nj * 8];     s[nj][3] += bp1[nj * 8 + 1];
            mx0 = fmaxf(mx0, fmaxf(s[nj][0], s[nj][1]));
            mx1 = fmaxf(mx1, fmaxf(s[nj][2], s[nj][3]));
        }
        mx0 = fmaxf(mx0, __shfl_xor_sync(0xffffffffu, mx0, 1));
        mx0 = fmaxf(mx0, __shfl_xor_sync(0xffffffffu, mx0, 2));
        mx1 = fmaxf(mx1, __shfl_xor_sync(0xffffffffu, mx1, 1));
        mx1 = fmaxf(mx1, __shfl_xor_sync(0xffffffffu, mx1, 2));
        float c0 = exp2f((m0r - mx0) * LOG2E);
        float c1 = exp2f((m1r - mx1) * LOG2E);
        m0r = mx0; m1r = mx1;
        float sum0 = 0.f, sum1 = 0.f;
        #pragma unroll
        for (int nj = 0; nj < 8; nj++) {
            s[nj][0] = exp2f((s[nj][0] - mx0) * LOG2E);
            s[nj][1] = exp2f((s[nj][1] - mx0) * LOG2E);
            s[nj][2] = exp2f((s[nj][2] - mx1) * LOG2E);
            s[nj][3] = exp2f((s[nj][3] - mx1) * LOG2E);
            sum0 += s[nj][0] + s[nj][1];
            sum1 += s[nj][2] + s[nj][3];
        }
        sum0 += __shfl_xor_sync(0xffffffffu, sum0, 1);
        sum0 += __shfl_xor_sync(0xffffffffu, sum0, 2);
        sum1 += __shfl_xor_sync(0xffffffffu, sum1, 1);
        sum1 += __shfl_xor_sync(0xffffffffu, sum1, 2);
        l0 = l0 * c0 + sum0;
        l1 = l1 * c1 + sum1;
        #pragma unroll
        for (int nd = 0; nd < 8; nd++) {
            O[nd][0] *= c0; O[nd][1] *= c0; O[nd][2] *= c1; O[nd][3] *= c1;
        }

        // P acc -> A-fragments, then PV
        uint32_t pf[4][4];
        #pragma unroll
        for (int kv = 0; kv < 4; kv++) {
            pf[kv][0] = packh2(s[2*kv][0],   s[2*kv][1]);
            pf[kv][1] = packh2(s[2*kv][2],   s[2*kv][3]);
            pf[kv][2] = packh2(s[2*kv+1][0], s[2*kv+1][1]);
            pf[kv][3] = packh2(s[2*kv+1][2], s[2*kv+1][3]);
        }
        #pragma unroll
        for (int kv = 0; kv < 4; kv++) {
            int krow = kv * 16 + rsel;
            #pragma unroll
            for (int ndp = 0; ndp < 4; ndp++) {
                int seg = 2 * ndp + chalf;
                uint32_t off = krow * 128 + ((seg ^ (krow & 7)) << 4);
                uint32_t vb[4];
                ldsm4t(vb, kb + 16384 + off);
                hmma(O[2*ndp],   pf[kv], vb[0], vb[1]);
                hmma(O[2*ndp+1], pf[kv], vb[2], vb[3]);
            }
        }
        __syncthreads();
    }

    // epilogue: ctx hi/lo row-major [b*S+q][h*64+d]
    float inv0 = 1.0f / l0, inv1 = 1.0f / l1;
    #pragma unroll
    for (int rr = 0; rr < 2; rr++) {
        int q = q0 + wid * 16 + g + rr * 8;
        float inv = rr ? inv1 : inv0;
        size_t base = ((size_t)(b * SEQ + q)) * DM + h * DKV + q2;
        #pragma unroll
        for (int nd = 0; nd < 8; nd++) {
            float v0 = O[nd][rr * 2] * inv, v1 = O[nd][rr * 2 + 1] * inv;
            __half h0, h1, lo0, lo1;
            split2(v0, h0, lo0); split2(v1, h1, lo1);
            __half2 ph = __halves2half2(h0, h1), pl = __halves2half2(lo0, lo1);
            *(uint32_t*)(g_ch + base + nd * 8) = *(uint32_t*)&ph;
            *(uint32_t*)(g_cl + base + nd * 8) = *(uint32_t*)&pl;
        }
    }
}

// ---------------------------------------------------------------------------
extern "C" void kernel_launch(void* const* d_in, const int* in_sizes, int n_in,
                              void* d_out, int out_size)
{
    const float* x   = (const float*)d_in[0];
    const float* wq  = (const float*)d_in[1];
    const float* wk  = (const float*)d_in[2];
    const float* wv  = (const float*)d_in[3];
    const float* wo  = (const float*)d_in[4];
    const float* rel = (const float*)d_in[5];
    float* out = (float*)d_out;

    __half *xh,*xl,*wth,*wtl,*qh,*ql,*kh,*kl,*vh,*ch,*cl;
    cudaGetSymbolAddress((void**)&xh, g_xh);  cudaGetSymbolAddress((void**)&xl, g_xl);
    cudaGetSymbolAddress((void**)&wth, g_wth); cudaGetSymbolAddress((void**)&wtl, g_wtl);
    cudaGetSymbolAddress((void**)&qh, g_qh);  cudaGetSymbolAddress((void**)&ql, g_ql);
    cudaGetSymbolAddress((void**)&kh, g_kh);  cudaGetSymbolAddress((void**)&kl, g_kl);
    cudaGetSymbolAddress((void**)&vh, g_vh);
    cudaGetSymbolAddress((void**)&ch, g_ch);  cudaGetSymbolAddress((void**)&cl, g_cl);

    cudaFuncSetAttribute(gemm_mma, cudaFuncAttributeMaxDynamicSharedMemorySize, G_SMEM);
    cudaFuncSetAttribute(attn_mma, cudaFuncAttributeMaxDynamicSharedMemorySize, AT_SMEM);

    split_x_kernel<<<MTOT*DM/1024, 256>>>(x);
    dim3 wg(32, 32), wb(32, 8);
    wsplitT_kernel<<<wg, wb>>>(wq, wth + 0*(size_t)DM*DM, wtl + 0*(size_t)DM*DM);
    wsplitT_kernel<<<wg, wb>>>(wk, wth + 1*(size_t)DM*DM, wtl + 1*(size_t)DM*DM);
    wsplitT_kernel<<<wg, wb>>>(wv, wth + 2*(size_t)DM*DM, wtl + 2*(size_t)DM*DM);
    wsplitT_kernel<<<wg, wb>>>(wo, wth + 3*(size_t)DM*DM, wtl + 3*(size_t)DM*DM);

    dim3 gg(DM/128, MTOT/128);
    gemm_mma<<<gg, 256, G_SMEM>>>(xh, xl, wth + 0*(size_t)DM*DM, wtl + 0*(size_t)DM*DM, nullptr, qh, ql, 1);
    gemm_mma<<<gg, 256, G_SMEM>>>(xh, xl, wth + 1*(size_t)DM*DM, wtl + 1*(size_t)DM*DM, nullptr, kh, kl, 1);
    gemm_mma<<<gg, 256, G_SMEM>>>(xh, xl, wth + 2*(size_t)DM*DM, wtl + 2*(size_t)DM*DM, nullptr, vh, nullptr, 2);
    attn_mma<<<dim3(SEQ/128, NH, BATCH), 256, AT_SMEM>>>(rel);
    gemm_mma<<<gg, 256, G_SMEM>>>(ch, cl, wth + 3*(size_t)DM*DM, wtl + 3*(size_t)DM*DM, out, nullptr, nullptr, 0);
}

// round 9
// speedup vs baseline: 2.6719x; 1.0636x over previous
#include <cuda_runtime.h>
#include <cuda_fp16.h>
#include <stdint.h>
#include <math.h>

#define SEQ   2048
#define BATCH 2
#define NH    16
#define DKV   64
#define DM    1024
#define MTOT  (BATCH*SEQ)
#define LOG2E 1.44269504f

// ---- static device scratch (no allocs) ----
__device__ __align__(16) __half g_xh[MTOT*DM], g_xl[MTOT*DM];
__device__ __align__(16) __half g_wth[4][DM*DM], g_wtl[4][DM*DM];
__device__ __align__(16) __half g_qh[BATCH*NH*SEQ*DKV], g_ql[BATCH*NH*SEQ*DKV];
__device__ __align__(16) __half g_kh[BATCH*NH*SEQ*DKV], g_kl[BATCH*NH*SEQ*DKV];
__device__ __align__(16) __half g_vh[BATCH*NH*SEQ*DKV];
__device__ __align__(16) __half g_ch[MTOT*DM], g_cl[MTOT*DM];

// ---- helpers ----
__device__ __forceinline__ uint32_t smem_u32(const void* p) {
    uint32_t a;
    asm("{ .reg .u64 t; cvta.to.shared.u64 t, %1; cvt.u32.u64 %0, t; }" : "=r"(a) : "l"(p));
    return a;
}
__device__ __forceinline__ void hmma(float* d, const uint32_t* a, uint32_t b0, uint32_t b1) {
    asm volatile("mma.sync.aligned.m16n8k16.row.col.f32.f16.f16.f32 "
        "{%0,%1,%2,%3}, {%4,%5,%6,%7}, {%8,%9}, {%0,%1,%2,%3};"
        : "+f"(d[0]), "+f"(d[1]), "+f"(d[2]), "+f"(d[3])
        : "r"(a[0]), "r"(a[1]), "r"(a[2]), "r"(a[3]), "r"(b0), "r"(b1));
}
__device__ __forceinline__ void ldsm4(uint32_t* r, uint32_t addr) {
    asm volatile("ldmatrix.sync.aligned.m8n8.x4.shared.b16 {%0,%1,%2,%3}, [%4];"
        : "=r"(r[0]), "=r"(r[1]), "=r"(r[2]), "=r"(r[3]) : "r"(addr));
}
__device__ __forceinline__ void ldsm4t(uint32_t* r, uint32_t addr) {
    asm volatile("ldmatrix.sync.aligned.m8n8.x4.trans.shared.b16 {%0,%1,%2,%3}, [%4];"
        : "=r"(r[0]), "=r"(r[1]), "=r"(r[2]), "=r"(r[3]) : "r"(addr));
}
__device__ __forceinline__ void cpa(uint32_t dst, const void* src) {
    asm volatile("cp.async.cg.shared.global [%0], [%1], 16;" :: "r"(dst), "l"(src));
}
#define CP_COMMIT() asm volatile("cp.async.commit_group;" ::: "memory")
#define CP_WAIT2()  asm volatile("cp.async.wait_group 2;" ::: "memory")
#define CP_WAIT1()  asm volatile("cp.async.wait_group 1;" ::: "memory")
#define CP_WAIT0()  asm volatile("cp.async.wait_group 0;" ::: "memory")

__device__ __forceinline__ void split2(float v, __half& hi, __half& lo) {
    hi = __float2half_rn(v);
    lo = __float2half_rn(v - __half2float(hi));
}
__device__ __forceinline__ uint32_t packh2(float a, float b) {
    __half2 h = __floats2half2_rn(a, b);
    return *(uint32_t*)&h;
}

// ---- prep ----
__global__ __launch_bounds__(256) void split_x_kernel(const float* __restrict__ x) {
    int i = (blockIdx.x * 256 + threadIdx.x) * 4;
    float4 v = *(const float4*)(x + i);
    __half h0,h1,h2,h3,l0,l1,l2,l3;
    split2(v.x,h0,l0); split2(v.y,h1,l1); split2(v.z,h2,l2); split2(v.w,h3,l3);
    __half2 hh[2] = { __halves2half2(h0,h1), __halves2half2(h2,h3) };
    __half2 ll[2] = { __halves2half2(l0,l1), __halves2half2(l2,l3) };
    *(uint2*)(g_xh + i) = *(uint2*)hh;
    *(uint2*)(g_xl + i) = *(uint2*)ll;
}
__global__ __launch_bounds__(256) void wsplitT_kernel(const float* __restrict__ W, int widx) {
    __shared__ float t[32][33];
    int n0 = blockIdx.x * 32, k0 = blockIdx.y * 32;
    int tx = threadIdx.x, ty = threadIdx.y;
    #pragma unroll
    for (int i = 0; i < 32; i += 8)
        t[ty + i][tx] = W[(size_t)(k0 + ty + i) * DM + n0 + tx];
    __syncthreads();
    #pragma unroll
    for (int i = 0; i < 32; i += 8) {
        int n = n0 + ty + i, k = k0 + tx;
        __half hi, lo; split2(t[tx][ty + i], hi, lo);
        g_wth[widx][(size_t)n * DM + k] = hi;
        g_wtl[widx][(size_t)n * DM + k] = lo;
    }
}

// ---- split-fp16 MMA GEMM mainloop (K-chunk 32, 3-stage cp.async) ----
#define GS_BUF 32768
#define G_SMEM (3*GS_BUF)
#define NCH    32

__device__ __forceinline__ void g_issue(uint32_t smb, const __half* const* mats,
                                        int c, int tid) {
    if (c < NCH) {
        uint32_t bufb = smb + (c % 3) * GS_BUF;
        #pragma unroll
        for (int i = 0; i < 8; i++) {
            int u = tid + i * 256;
            int mat = u >> 9, rem = u & 511, row = rem >> 2, seg = rem & 3;
            const void* src = mats[mat] + (size_t)row * DM + c * 32 + seg * 8;
            uint32_t dst = bufb + mat * 8192 + row * 64 + ((seg ^ ((row >> 1) & 3)) << 4);
            cpa(dst, src);
        }
    }
    CP_COMMIT();
}

__device__ __forceinline__ void g_mainloop(uint32_t smb, const __half* const* mats,
                                           float acc[2][8][4], int tid) {
    const int lane = tid & 31, wid = tid >> 5;
    const int wm = wid >> 1, wn = wid & 1;
    const int rsel = (lane & 7) + ((lane >> 3) & 1) * 8;
    const int chalf = lane >> 4;

    g_issue(smb, mats, 0, tid);
    g_issue(smb, mats, 1, tid);
    for (int c = 0; c < NCH; c++) {
        g_issue(smb, mats, c + 2, tid);
        CP_WAIT2();
        __syncthreads();
        uint32_t ab = smb + (c % 3) * GS_BUF;
        #pragma unroll
        for (int ks = 0; ks < 2; ks++) {
            int sseg = 2 * ks + chalf;
            uint32_t ah[2][4], al_[2][4];
            #pragma unroll
            for (int mi = 0; mi < 2; mi++) {
                int row = wm * 32 + mi * 16 + rsel;
                uint32_t off = row * 64 + ((sseg ^ ((row >> 1) & 3)) << 4);
                ldsm4(ah[mi], ab + off);
                ldsm4(al_[mi], ab + 8192 + off);
            }
            #pragma unroll
            for (int njp = 0; njp < 4; njp++) {
                int row = wn * 64 + njp * 16 + rsel;
                uint32_t off = row * 64 + ((sseg ^ ((row >> 1) & 3)) << 4);
                uint32_t bh_[4], bl_[4];
                ldsm4(bh_, ab + 16384 + off);
                ldsm4(bl_, ab + 24576 + off);
                #pragma unroll
                for (int mi = 0; mi < 2; mi++) {
                    hmma(acc[mi][2*njp],   ah[mi],  bh_[0], bh_[2]);
                    hmma(acc[mi][2*njp+1], ah[mi],  bh_[1], bh_[3]);
                    hmma(acc[mi][2*njp],   ah[mi],  bl_[0], bl_[2]);
                    hmma(acc[mi][2*njp+1], ah[mi],  bl_[1], bl_[3]);
                    hmma(acc[mi][2*njp],   al_[mi], bh_[0], bh_[2]);
                    hmma(acc[mi][2*njp+1], al_[mi], bh_[1], bh_[3]);
                }
            }
        }
        __syncthreads();
    }
}

// Fused QKV projection: z = 0(Q, hi/lo), 1(K, hi/lo), 2(V, hi-only)
__global__ __launch_bounds__(256, 2) void qkv_gemm() {
    extern __shared__ char smg[];
    uint32_t smb = smem_u32(smg);
    const int tid = threadIdx.x, lane = tid & 31, wid = tid >> 5;
    const int m0 = blockIdx.y * 128, n0 = blockIdx.x * 128, z = blockIdx.z;
    const int wm = wid >> 1, wn = wid & 1;

    const __half* mats[4] = { g_xh + (size_t)m0 * DM, g_xl + (size_t)m0 * DM,
                              g_wth[z] + (size_t)n0 * DM, g_wtl[z] + (size_t)n0 * DM };
    float acc[2][8][4];
    #pragma unroll
    for (int i = 0; i < 2; i++)
        #pragma unroll
        for (int j = 0; j < 8; j++)
            #pragma unroll
            for (int e = 0; e < 4; e++) acc[i][j][e] = 0.f;

    g_mainloop(smb, mats, acc, tid);

    __half* Oh = (z == 0) ? g_qh : (z == 1) ? g_kh : g_vh;
    __half* Ol = (z == 0) ? g_ql : g_kl;
    const int g = lane >> 2, q2 = (lane & 3) * 2;
    #pragma unroll
    for (int mi = 0; mi < 2; mi++)
        #pragma unroll
        for (int rr = 0; rr < 2; rr++) {
            int m = m0 + wm * 32 + mi * 16 + g + rr * 8;
            int bb = m >> 11, ss = m & (SEQ - 1);
            #pragma unroll
            for (int nj = 0; nj < 8; nj++) {
                float v0 = acc[mi][nj][rr * 2], v1 = acc[mi][nj][rr * 2 + 1];
                int n = n0 + wn * 64 + nj * 8 + q2;
                int hh = n >> 6, dd = n & 63;
                size_t off = (((size_t)(bb * NH + hh)) * SEQ + ss) * DKV + dd;
                __half h0, h1, l0, l1;
                split2(v0, h0, l0); split2(v1, h1, l1);
                __half2 ph = __halves2half2(h0, h1);
                *(uint32_t*)(Oh + off) = *(uint32_t*)&ph;
                if (z < 2) {
                    __half2 pl = __halves2half2(l0, l1);
                    *(uint32_t*)(Ol + off) = *(uint32_t*)&pl;
                }
            }
        }
}

// Output GEMM: out = ctx @ wo (fp32 row-major)
__global__ __launch_bounds__(256, 2) void out_gemm(float* __restrict__ Cf) {
    extern __shared__ char smg[];
    uint32_t smb = smem_u32(smg);
    const int tid = threadIdx.x, lane = tid & 31, wid = tid >> 5;
    const int m0 = blockIdx.y * 128, n0 = blockIdx.x * 128;
    const int wm = wid >> 1, wn = wid & 1;

    const __half* mats[4] = { g_ch + (size_t)m0 * DM, g_cl + (size_t)m0 * DM,
                              g_wth[3] + (size_t)n0 * DM, g_wtl[3] + (size_t)n0 * DM };
    float acc[2][8][4];
    #pragma unroll
    for (int i = 0; i < 2; i++)
        #pragma unroll
        for (int j = 0; j < 8; j++)
            #pragma unroll
            for (int e = 0; e < 4; e++) acc[i][j][e] = 0.f;

    g_mainloop(smb, mats, acc, tid);

    const int g = lane >> 2, q2 = (lane & 3) * 2;
    #pragma unroll
    for (int mi = 0; mi < 2; mi++)
        #pragma unroll
        for (int rr = 0; rr < 2; rr++) {
            int m = m0 + wm * 32 + mi * 16 + g + rr * 8;
            #pragma unroll
            for (int nj = 0; nj < 8; nj++) {
                int n = n0 + wn * 64 + nj * 8 + q2;
                *(float2*)(Cf + (size_t)m * DM + n) =
                    make_float2(acc[mi][nj][rr * 2], acc[mi][nj][rr * 2 + 1]);
            }
        }
}

// ---- FA2-style mma.sync flash attention ----
#define AT_QH 0
#define AT_QL 16384
#define AT_KV 32768            /* 2 bufs x 24576 (Kh 8K | Kl 8K | V 8K) */
#define AT_BI 81920
#define AT_SMEM (81920 + 2176*4)

__device__ __forceinline__ void attn_issue(uint32_t smb, const __half* kh, const __half* kl,
                                           const __half* vh, int t, int buf, int tid) {
    #pragma unroll
    for (int i = 0; i < 6; i++) {
        int u = tid + i * 256;
        int mat = u >> 9, rem = u & 511, row = rem >> 3, seg = rem & 7;
        const __half* base = (mat == 0) ? kh : (mat == 1) ? kl : vh;
        const void* src = base + (size_t)(t * 64 + row) * DKV + seg * 8;
        uint32_t dst = smb + AT_KV + buf * 24576 + mat * 8192 + row * 128 + ((seg ^ (row & 7)) << 4);
        cpa(dst, src);
    }
    CP_COMMIT();
}

__global__ __launch_bounds__(256, 2) void attn_mma(const float* __restrict__ rel_emb)
{
    extern __shared__ char smn[];
    uint32_t smb = smem_u32(smn);
    const int tid = threadIdx.x, lane = tid & 31, wid = tid >> 5;
    const int b = blockIdx.z, h = blockIdx.y, q0 = blockIdx.x * 128;
    const size_t hoff = ((size_t)(b * NH + h)) * SEQ * DKV;
    const __half* kh = g_kh + hoff;
    const __half* kl = g_kl + hoff;
    const __half* vh = g_vh + hoff;

    attn_issue(smb, kh, kl, vh, 0, 0, tid);

    // Q staging (hi/lo), swizzled (128B rows)
    #pragma unroll
    for (int i = 0; i < 8; i++) {
        int u = tid + i * 256;
        int mat = u >> 10, rem = u & 1023, row = rem >> 3, seg = rem & 7;
        const uint4* src = (const uint4*)(((mat == 0) ? g_qh : g_ql) + hoff
                             + (size_t)(q0 + row) * DKV + seg * 8);
        *(uint4*)(smn + mat * 16384 + row * 128 + ((seg ^ (row & 7)) << 4)) = *src;
    }
    // bias table (exact reference bucket math)
    float* biasS = (float*)(smn + AT_BI);
    for (int j = tid; j < 2175; j += 256) {
        int rel = j - (q0 + 127);
        int n = -rel, ret = 0;
        if (n < 0) { ret = 16; n = -n; }
        int bkt;
        if (n < 8) bkt = n;
        else {
            float t = logf((float)n * 0.125f) / 2.7725887222397812f * 8.0f;
            int v = 8 + (int)t;
            bkt = v < 15 ? v : 15;
        }
        biasS[j] = __ldg(&rel_emb[(ret + bkt) * NH + h]);
    }
    __syncthreads();

    const int rsel = (lane & 7) + ((lane >> 3) & 1) * 8;
    const int chalf = lane >> 4;
    const int qrow = wid * 16 + rsel;
    // Q-hi fragments resident; Q-lo reloaded from smem per tile (reg pressure)
    uint32_t qfh[4][4];
    #pragma unroll
    for (int ks = 0; ks < 4; ks++) {
        int seg = 2 * ks + chalf;
        ldsm4(qfh[ks], smb + AT_QH + qrow * 128 + ((seg ^ (qrow & 7)) << 4));
    }

    float O[8][4];
    #pragma unroll
    for (int j = 0; j < 8; j++)
        #pragma unroll
        for (int e = 0; e < 4; e++) O[j][e] = 0.f;
    float m0r = -1e30f, m1r = -1e30f, l0 = 0.f, l1 = 0.f;
    const int g = lane >> 2, q2 = (lane & 3) * 2;
    const int qr0 = wid * 16 + g;

    for (int t = 0; t < 32; t++) {
        if (t < 31) { attn_issue(smb, kh, kl, vh, t + 1, (t + 1) & 1, tid); CP_WAIT1(); }
        else CP_WAIT0();
        __syncthreads();
        uint32_t kb = smb + AT_KV + (t & 1) * 24576;

        float s[8][4];
        #pragma unroll
        for (int j = 0; j < 8; j++)
            #pragma unroll
            for (int e = 0; e < 4; e++) s[j][e] = 0.f;

        #pragma unroll
        for (int ks = 0; ks < 4; ks++) {
            int sseg = 2 * ks + chalf;
            uint32_t qfl[4];
            ldsm4(qfl, smb + AT_QL + qrow * 128 + ((sseg ^ (qrow & 7)) << 4));
            #pragma unroll
            for (int njp = 0; njp < 4; njp++) {
                int row = njp * 16 + rsel;
                uint32_t off = row * 128 + ((sseg ^ (row & 7)) << 4);
                uint32_t kbh[4], kbl[4];
                ldsm4(kbh, kb + off);
                ldsm4(kbl, kb + 8192 + off);
                hmma(s[2*njp],   qfh[ks], kbh[0], kbh[2]);
                hmma(s[2*njp+1], qfh[ks], kbh[1], kbh[3]);
                hmma(s[2*njp],   qfh[ks], kbl[0], kbl[2]);
                hmma(s[2*njp+1], qfh[ks], kbl[1], kbl[3]);
                hmma(s[2*njp],   qfl,     kbh[0], kbh[2]);
                hmma(s[2*njp+1], qfl,     kbh[1], kbh[3]);
            }
        }

        // bias + in-register online softmax (rows qr0, qr0+8)
        const float* bp0 = biasS + t * 64 + q2 + 127 - qr0;
        const float* bp1 = bp0 - 8;
        float mx0 = m0r, mx1 = m1r;
        #pragma unroll
        for (int nj = 0; nj < 8; nj++) {
            s[nj][0] += bp0[nj * 8];     s[nj][1] += bp0[nj * 8 + 1];
            s[nj][2] += bp1[nj * 8];     s[nj][3] += bp1[nj * 8 + 1];
            mx0 = fmaxf(mx0, fmaxf(s[nj][0], s[nj][1]));
            mx1 = fmaxf(mx1, fmaxf(s[nj][2], s[nj][3]));
        }
        mx0 = fmaxf(mx0, __shfl_xor_sync(0xffffffffu, mx0, 1));
        mx0 = fmaxf(mx0, __shfl_xor_sync(0xffffffffu, mx0, 2));
        mx1 = fmaxf(mx1, __shfl_xor_sync(0xffffffffu, mx1, 1));
        mx1 = fmaxf(mx1, __shfl_xor_sync(0xffffffffu, mx1, 2));
        float c0 = exp2f((m0r - mx0) * LOG2E);
        float c1 = exp2f((m1r - mx1) * LOG2E);
        m0r = mx0; m1r = mx1;
        float sum0 = 0.f, sum1 = 0.f;
        #pragma unroll
        for (int nj = 0; nj < 8; nj++) {
            s[nj][0] = exp2f((s[nj][0] - mx0) * LOG2E);
            s[nj][1] = exp2f((s[nj][1] - mx0) * LOG2E);
            s[nj][2] = exp2f((s[nj][2] - mx1) * LOG2E);
            s[nj][3] = exp2f((s[nj][3] - mx1) * LOG2E);
            sum0 += s[nj][0] + s[nj][1];
            sum1 += s[nj][2] + s[nj][3];
        }
        sum0 += __shfl_xor_sync(0xffffffffu, sum0, 1);
        sum0 += __shfl_xor_sync(0xffffffffu, sum0, 2);
        sum1 += __shfl_xor_sync(0xffffffffu, sum1, 1);
        sum1 += __shfl_xor_sync(0xffffffffu, sum1, 2);
        l0 = l0 * c0 + sum0;
        l1 = l1 * c1 + sum1;
        #pragma unroll
        for (int nd = 0; nd < 8; nd++) {
            O[nd][0] *= c0; O[nd][1] *= c0; O[nd][2] *= c1; O[nd][3] *= c1;
        }

        // P acc -> A-fragments, then PV
        #pragma unroll
        for (int kv = 0; kv < 4; kv++) {
            uint32_t pf[4];
            pf[0] = packh2(s[2*kv][0],   s[2*kv][1]);
            pf[1] = packh2(s[2*kv][2],   s[2*kv][3]);
            pf[2] = packh2(s[2*kv+1][0], s[2*kv+1][1]);
            pf[3] = packh2(s[2*kv+1][2], s[2*kv+1][3]);
            int krow = kv * 16 + rsel;
            #pragma unroll
            for (int ndp = 0; ndp < 4; ndp++) {
                int seg = 2 * ndp + chalf;
                uint32_t off = krow * 128 + ((seg ^ (krow & 7)) << 4);
                uint32_t vb[4];
                ldsm4t(vb, kb + 16384 + off);
                hmma(O[2*ndp],   pf, vb[0], vb[1]);
                hmma(O[2*ndp+1], pf, vb[2], vb[3]);
            }
        }
        __syncthreads();
    }

    // epilogue: ctx hi/lo row-major [b*S+q][h*64+d]
    float inv0 = 1.0f / l0, inv1 = 1.0f / l1;
    #pragma unroll
    for (int rr = 0; rr < 2; rr++) {
        int q = q0 + wid * 16 + g + rr * 8;
        float inv = rr ? inv1 : inv0;
        size_t base = ((size_t)(b * SEQ + q)) * DM + h * DKV + q2;
        #pragma unroll
        for (int nd = 0; nd < 8; nd++) {
            float v0 = O[nd][rr * 2] * inv, v1 = O[nd][rr * 2 + 1] * inv;
            __half h0, h1, lo0, lo1;
            split2(v0, h0, lo0); split2(v1, h1, lo1);
            __half2 ph = __halves2half2(h0, h1), pl = __halves2half2(lo0, lo1);
            *(uint32_t*)(g_ch + base + nd * 8) = *(uint32_t*)&ph;
            *(uint32_t*)(g_cl + base + nd * 8) = *(uint32_t*)&pl;
        }
    }
}

// ---------------------------------------------------------------------------
extern "C" void kernel_launch(void* const* d_in, const int* in_sizes, int n_in,
                              void* d_out, int out_size)
{
    const float* x   = (const float*)d_in[0];
    const float* wq  = (const float*)d_in[1];
    const float* wk  = (const float*)d_in[2];
    const float* wv  = (const float*)d_in[3];
    const float* wo  = (const float*)d_in[4];
    const float* rel = (const float*)d_in[5];
    float* out = (float*)d_out;

    cudaFuncSetAttribute(qkv_gemm, cudaFuncAttributeMaxDynamicSharedMemorySize, G_SMEM);
    cudaFuncSetAttribute(out_gemm, cudaFuncAttributeMaxDynamicSharedMemorySize, G_SMEM);
    cudaFuncSetAttribute(attn_mma, cudaFuncAttributeMaxDynamicSharedMemorySize, AT_SMEM);

    split_x_kernel<<<MTOT*DM/1024, 256>>>(x);
    dim3 wg(32, 32), wb(32, 8);
    wsplitT_kernel<<<wg, wb>>>(wq, 0);
    wsplitT_kernel<<<wg, wb>>>(wk, 1);
    wsplitT_kernel<<<wg, wb>>>(wv, 2);
    wsplitT_kernel<<<wg, wb>>>(wo, 3);

    qkv_gemm<<<dim3(DM/128, MTOT/128, 3), 256, G_SMEM>>>();
    attn_mma<<<dim3(SEQ/128, NH, BATCH), 256, AT_SMEM>>>(rel);
    out_gemm<<<dim3(DM/128, MTOT/128), 256, G_SMEM>>>(out);
}

// round 11
// speedup vs baseline: 4.3970x; 1.6456x over previous
#include <cuda_runtime.h>
#include <cuda_fp16.h>
#include <stdint.h>
#include <math.h>

#define SEQ   2048
#define BATCH 2
#define NH    16
#define DKV   64
#define DM    1024
#define MTOT  (BATCH*SEQ)
#define LOG2E 1.44269504f

// ---- static device scratch (no allocs) ----
__device__ __align__(16) __half g_xh[MTOT*DM], g_xl[MTOT*DM];
__device__ __align__(16) __half g_wth[4][DM*DM], g_wtl[4][DM*DM];
__device__ __align__(16) __half g_qh[BATCH*NH*SEQ*DKV], g_ql[BATCH*NH*SEQ*DKV];
__device__ __align__(16) __half g_kh[BATCH*NH*SEQ*DKV], g_kl[BATCH*NH*SEQ*DKV];
__device__ __align__(16) __half g_vh[BATCH*NH*SEQ*DKV];
__device__ __align__(16) __half g_ch[MTOT*DM];

// ---- helpers ----
__device__ __forceinline__ uint32_t smem_u32(const void* p) {
    uint32_t a;
    asm("{ .reg .u64 t; cvta.to.shared.u64 t, %1; cvt.u32.u64 %0, t; }" : "=r"(a) : "l"(p));
    return a;
}
__device__ __forceinline__ void hmma(float* d, const uint32_t* a, uint32_t b0, uint32_t b1) {
    asm volatile("mma.sync.aligned.m16n8k16.row.col.f32.f16.f16.f32 "
        "{%0,%1,%2,%3}, {%4,%5,%6,%7}, {%8,%9}, {%0,%1,%2,%3};"
        : "+f"(d[0]), "+f"(d[1]), "+f"(d[2]), "+f"(d[3])
        : "r"(a[0]), "r"(a[1]), "r"(a[2]), "r"(a[3]), "r"(b0), "r"(b1));
}
__device__ __forceinline__ void ldsm4(uint32_t* r, uint32_t addr) {
    asm volatile("ldmatrix.sync.aligned.m8n8.x4.shared.b16 {%0,%1,%2,%3}, [%4];"
        : "=r"(r[0]), "=r"(r[1]), "=r"(r[2]), "=r"(r[3]) : "r"(addr));
}
__device__ __forceinline__ void ldsm4t(uint32_t* r, uint32_t addr) {
    asm volatile("ldmatrix.sync.aligned.m8n8.x4.trans.shared.b16 {%0,%1,%2,%3}, [%4];"
        : "=r"(r[0]), "=r"(r[1]), "=r"(r[2]), "=r"(r[3]) : "r"(addr));
}
__device__ __forceinline__ void cpa(uint32_t dst, const void* src) {
    asm volatile("cp.async.cg.shared.global [%0], [%1], 16;" :: "r"(dst), "l"(src));
}
#define CP_COMMIT() asm volatile("cp.async.commit_group;" ::: "memory")
#define CP_WAIT2()  asm volatile("cp.async.wait_group 2;" ::: "memory")
#define CP_WAIT1()  asm volatile("cp.async.wait_group 1;" ::: "memory")
#define CP_WAIT0()  asm volatile("cp.async.wait_group 0;" ::: "memory")

__device__ __forceinline__ void split2(float v, __half& hi, __half& lo) {
    hi = __float2half_rn(v);
    lo = __float2half_rn(v - __half2float(hi));
}
__device__ __forceinline__ uint32_t packh2(float a, float b) {
    __half2 h = __floats2half2_rn(a, b);
    return *(uint32_t*)&h;
}

// ---- prep ----
__global__ __launch_bounds__(256) void split_x_kernel(const float* __restrict__ x) {
    int i = (blockIdx.x * 256 + threadIdx.x) * 4;
    float4 v = *(const float4*)(x + i);
    __half h0,h1,h2,h3,l0,l1,l2,l3;
    split2(v.x,h0,l0); split2(v.y,h1,l1); split2(v.z,h2,l2); split2(v.w,h3,l3);
    __half2 hh[2] = { __halves2half2(h0,h1), __halves2half2(h2,h3) };
    __half2 ll[2] = { __halves2half2(l0,l1), __halves2half2(l2,l3) };
    *(uint2*)(g_xh + i) = *(uint2*)hh;
    *(uint2*)(g_xl + i) = *(uint2*)ll;
}
// two weights per launch (z selects) so attn_mma lands as the 5th launch for ncu
__global__ __launch_bounds__(256) void wsplit2_kernel(const float* __restrict__ Wa,
                                                      const float* __restrict__ Wb, int widx0) {
    __shared__ float t[32][33];
    const float* W = blockIdx.z ? Wb : Wa;
    int widx = widx0 + blockIdx.z;
    int n0 = blockIdx.x * 32, k0 = blockIdx.y * 32;
    int tx = threadIdx.x, ty = threadIdx.y;
    #pragma unroll
    for (int i = 0; i < 32; i += 8)
        t[ty + i][tx] = W[(size_t)(k0 + ty + i) * DM + n0 + tx];
    __syncthreads();
    #pragma unroll
    for (int i = 0; i < 32; i += 8) {
        int n = n0 + ty + i, k = k0 + tx;
        __half hi, lo; split2(t[tx][ty + i], hi, lo);
        g_wth[widx][(size_t)n * DM + k] = hi;
        g_wtl[widx][(size_t)n * DM + k] = lo;
    }
}

// ---- split-fp16 MMA GEMM mainloops (K-chunk 32, 3-stage cp.async) ----
#define GS_BUF  32768
#define G_SMEM  (3*GS_BUF)
#define GS3_BUF 24576
#define G3_SMEM (3*GS3_BUF)
#define NCH     32

__device__ __forceinline__ void g_issue(uint32_t smb, const __half* const* mats,
                                        int c, int tid) {
    if (c < NCH) {
        uint32_t bufb = smb + (c % 3) * GS_BUF;
        #pragma unroll
        for (int i = 0; i < 8; i++) {
            int u = tid + i * 256;
            int mat = u >> 9, rem = u & 511, row = rem >> 2, seg = rem & 3;
            const void* src = mats[mat] + (size_t)row * DM + c * 32 + seg * 8;
            uint32_t dst = bufb + mat * 8192 + row * 64 + ((seg ^ ((row >> 1) & 3)) << 4);
            cpa(dst, src);
        }
    }
    CP_COMMIT();
}

// 3-term: acc += Ah*Bh + Ah*Bl + Al*Bh    (mats = {Ah, Al, Bh, Bl})
__device__ __forceinline__ void g_mainloop(uint32_t smb, const __half* const* mats,
                                           float acc[2][8][4], int tid) {
    const int lane = tid & 31, wid = tid >> 5;
    const int wm = wid >> 1, wn = wid & 1;
    const int rsel = (lane & 7) + ((lane >> 3) & 1) * 8;
    const int chalf = lane >> 4;

    g_issue(smb, mats, 0, tid);
    g_issue(smb, mats, 1, tid);
    for (int c = 0; c < NCH; c++) {
        g_issue(smb, mats, c + 2, tid);
        CP_WAIT2();
        __syncthreads();
        uint32_t ab = smb + (c % 3) * GS_BUF;
        #pragma unroll
        for (int ks = 0; ks < 2; ks++) {
            int sseg = 2 * ks + chalf;
            uint32_t ah[2][4], al_[2][4];
            #pragma unroll
            for (int mi = 0; mi < 2; mi++) {
                int row = wm * 32 + mi * 16 + rsel;
                uint32_t off = row * 64 + ((sseg ^ ((row >> 1) & 3)) << 4);
                ldsm4(ah[mi], ab + off);
                ldsm4(al_[mi], ab + 8192 + off);
            }
            #pragma unroll
            for (int njp = 0; njp < 4; njp++) {
                int row = wn * 64 + njp * 16 + rsel;
                uint32_t off = row * 64 + ((sseg ^ ((row >> 1) & 3)) << 4);
                uint32_t bh_[4], bl_[4];
                ldsm4(bh_, ab + 16384 + off);
                ldsm4(bl_, ab + 24576 + off);
                #pragma unroll
                for (int mi = 0; mi < 2; mi++) {
                    hmma(acc[mi][2*njp],   ah[mi],  bh_[0], bh_[2]);
                    hmma(acc[mi][2*njp+1], ah[mi],  bh_[1], bh_[3]);
                    hmma(acc[mi][2*njp],   ah[mi],  bl_[0], bl_[2]);
                    hmma(acc[mi][2*njp+1], ah[mi],  bl_[1], bl_[3]);
                    hmma(acc[mi][2*njp],   al_[mi], bh_[0], bh_[2]);
                    hmma(acc[mi][2*njp+1], al_[mi], bh_[1], bh_[3]);
                }
            }
        }
        __syncthreads();
    }
}

__device__ __forceinline__ void g_issue3(uint32_t smb, const __half* const* mats,
                                         int c, int tid) {
    if (c < NCH) {
        uint32_t bufb = smb + (c % 3) * GS3_BUF;
        #pragma unroll
        for (int i = 0; i < 6; i++) {
            int u = tid + i * 256;
            int mat = u >> 9, rem = u & 511, row = rem >> 2, seg = rem & 3;
            const void* src = mats[mat] + (size_t)row * DM + c * 32 + seg * 8;
            uint32_t dst = bufb + mat * 8192 + row * 64 + ((seg ^ ((row >> 1) & 3)) << 4);
            cpa(dst, src);
        }
    }
    CP_COMMIT();
}

// 2-term: acc += A*Bh + A*Bl    (mats = {A, Bh, Bl})
__device__ __forceinline__ void g_mainloop3(uint32_t smb, const __half* const* mats,
                                            float acc[2][8][4], int tid) {
    const int lane = tid & 31, wid = tid >> 5;
    const int wm = wid >> 1, wn = wid & 1;
    const int rsel = (lane & 7) + ((lane >> 3) & 1) * 8;
    const int chalf = lane >> 4;

    g_issue3(smb, mats, 0, tid);
    g_issue3(smb, mats, 1, tid);
    for (int c = 0; c < NCH; c++) {
        g_issue3(smb, mats, c + 2, tid);
        CP_WAIT2();
        __syncthreads();
        uint32_t ab = smb + (c % 3) * GS3_BUF;
        #pragma unroll
        for (int ks = 0; ks < 2; ks++) {
            int sseg = 2 * ks + chalf;
            uint32_t ah[2][4];
            #pragma unroll
            for (int mi = 0; mi < 2; mi++) {
                int row = wm * 32 + mi * 16 + rsel;
                uint32_t off = row * 64 + ((sseg ^ ((row >> 1) & 3)) << 4);
                ldsm4(ah[mi], ab + off);
            }
            #pragma unroll
            for (int njp = 0; njp < 4; njp++) {
                int row = wn * 64 + njp * 16 + rsel;
                uint32_t off = row * 64 + ((sseg ^ ((row >> 1) & 3)) << 4);
                uint32_t bh_[4], bl_[4];
                ldsm4(bh_, ab + 8192 + off);
                ldsm4(bl_, ab + 16384 + off);
                #pragma unroll
                for (int mi = 0; mi < 2; mi++) {
                    hmma(acc[mi][2*njp],   ah[mi], bh_[0], bh_[2]);
                    hmma(acc[mi][2*njp+1], ah[mi], bh_[1], bh_[3]);
                    hmma(acc[mi][2*njp],   ah[mi], bl_[0], bl_[2]);
                    hmma(acc[mi][2*njp+1], ah[mi], bl_[1], bl_[3]);
                }
            }
        }
        __syncthreads();
    }
}

// Fused QKV projection: z = 0(Q, hi/lo), 1(K, hi/lo), 2(V, hi-only)
__global__ __launch_bounds__(256, 2) void qkv_gemm() {
    extern __shared__ char smg[];
    uint32_t smb = smem_u32(smg);
    const int tid = threadIdx.x, lane = tid & 31, wid = tid >> 5;
    const int m0 = blockIdx.y * 128, n0 = blockIdx.x * 128, z = blockIdx.z;
    const int wm = wid >> 1, wn = wid & 1;

    const __half* mats[4] = { g_xh + (size_t)m0 * DM, g_xl + (size_t)m0 * DM,
                              g_wth[z] + (size_t)n0 * DM, g_wtl[z] + (size_t)n0 * DM };
    float acc[2][8][4];
    #pragma unroll
    for (int i = 0; i < 2; i++)
        #pragma unroll
        for (int j = 0; j < 8; j++)
            #pragma unroll
            for (int e = 0; e < 4; e++) acc[i][j][e] = 0.f;

    g_mainloop(smb, mats, acc, tid);

    __half* Oh = (z == 0) ? g_qh : (z == 1) ? g_kh : g_vh;
    __half* Ol = (z == 0) ? g_ql : g_kl;
    const int g = lane >> 2, q2 = (lane & 3) * 2;
    #pragma unroll
    for (int mi = 0; mi < 2; mi++)
        #pragma unroll
        for (int rr = 0; rr < 2; rr++) {
            int m = m0 + wm * 32 + mi * 16 + g + rr * 8;
            int bb = m >> 11, ss = m & (SEQ - 1);
            #pragma unroll
            for (int nj = 0; nj < 8; nj++) {
                float v0 = acc[mi][nj][rr * 2], v1 = acc[mi][nj][rr * 2 + 1];
                int n = n0 + wn * 64 + nj * 8 + q2;
                int hh = n >> 6, dd = n & 63;
                size_t off = (((size_t)(bb * NH + hh)) * SEQ + ss) * DKV + dd;
                __half h0, h1, l0, l1;
                split2(v0, h0, l0); split2(v1, h1, l1);
                __half2 ph = __halves2half2(h0, h1);
                *(uint32_t*)(Oh + off) = *(uint32_t*)&ph;
                if (z < 2) {
                    __half2 pl = __halves2half2(l0, l1);
                    *(uint32_t*)(Ol + off) = *(uint32_t*)&pl;
                }
            }
        }
}

// Output GEMM: out = ctx_hi @ wo, 2-term (wo hi+lo), fp32 row-major
__global__ __launch_bounds__(256, 2) void out_gemm(float* __restrict__ Cf) {
    extern __shared__ char smg[];
    uint32_t smb = smem_u32(smg);
    const int tid = threadIdx.x, lane = tid & 31, wid = tid >> 5;
    const int m0 = blockIdx.y * 128, n0 = blockIdx.x * 128;
    const int wm = wid >> 1, wn = wid & 1;

    const __half* mats[3] = { g_ch + (size_t)m0 * DM,
                              g_wth[3] + (size_t)n0 * DM, g_wtl[3] + (size_t)n0 * DM };
    float acc[2][8][4];
    #pragma unroll
    for (int i = 0; i < 2; i++)
        #pragma unroll
        for (int j = 0; j < 8; j++)
            #pragma unroll
            for (int e = 0; e < 4; e++) acc[i][j][e] = 0.f;

    g_mainloop3(smb, mats, acc, tid);

    const int g = lane >> 2, q2 = (lane & 3) * 2;
    #pragma unroll
    for (int mi = 0; mi < 2; mi++)
        #pragma unroll
        for (int rr = 0; rr < 2; rr++) {
            int m = m0 + wm * 32 + mi * 16 + g + rr * 8;
            #pragma unroll
            for (int nj = 0; nj < 8; nj++) {
                int n = n0 + wn * 64 + nj * 8 + q2;
                *(float2*)(Cf + (size_t)m * DM + n) =
                    make_float2(acc[mi][nj][rr * 2], acc[mi][nj][rr * 2 + 1]);
            }
        }
}

// ---- FA2-style mma.sync flash attention ----
#define AT_QH 0
#define AT_QL 16384
#define AT_KV 32768            /* 2 bufs x 24576 (Kh 8K | Kl 8K | V 8K) */
#define AT_BI 81920
#define AT_SMEM (81920 + 2176*4)

__device__ __forceinline__ void attn_issue(uint32_t smb, const __half* kh, const __half* kl,
                                           const __half* vh, int t, int buf, int tid) {
    #pragma unroll
    for (int i = 0; i < 6; i++) {
        int u = tid + i * 256;
        int mat = u >> 9, rem = u & 511, row = rem >> 3, seg = rem & 7;
        const __half* base = (mat == 0) ? kh : (mat == 1) ? kl : vh;
        const void* src = base + (size_t)(t * 64 + row) * DKV + seg * 8;
        uint32_t dst = smb + AT_KV + buf * 24576 + mat * 8192 + row * 128 + ((seg ^ (row & 7)) << 4);
        cpa(dst, src);
    }
    CP_COMMIT();
}

__global__ __launch_bounds__(256, 2) void attn_mma(const float* __restrict__ rel_emb)
{
    extern __shared__ char smn[];
    uint32_t smb = smem_u32(smn);
    const int tid = threadIdx.x, lane = tid & 31, wid = tid >> 5;
    const int b = blockIdx.z, h = blockIdx.y, q0 = blockIdx.x * 128;
    const size_t hoff = ((size_t)(b * NH + h)) * SEQ * DKV;
    const __half* kh = g_kh + hoff;
    const __half* kl = g_kl + hoff;
    const __half* vh = g_vh + hoff;

    attn_issue(smb, kh, kl, vh, 0, 0, tid);

    // Q staging (hi/lo), swizzled (128B rows)
    #pragma unroll
    for (int i = 0; i < 8; i++) {
        int u = tid + i * 256;
        int mat = u >> 10, rem = u & 1023, row = rem >> 3, seg = rem & 7;
        const uint4* src = (const uint4*)(((mat == 0) ? g_qh : g_ql) + hoff
                             + (size_t)(q0 + row) * DKV + seg * 8);
        *(uint4*)(smn + mat * 16384 + row * 128 + ((seg ^ (row & 7)) << 4)) = *src;
    }
    // bias table (exact reference bucket math)
    float* biasS = (float*)(smn + AT_BI);
    for (int j = tid; j < 2175; j += 256) {
        int rel = j - (q0 + 127);
        int n = -rel, ret = 0;
        if (n < 0) { ret = 16; n = -n; }
        int bkt;
        if (n < 8) bkt = n;
        else {
            float t = logf((float)n * 0.125f) / 2.7725887222397812f * 8.0f;
            int v = 8 + (int)t;
            bkt = v < 15 ? v : 15;
        }
        biasS[j] = __ldg(&rel_emb[(ret + bkt) * NH + h]);
    }
    __syncthreads();

    const int rsel = (lane & 7) + ((lane >> 3) & 1) * 8;
    const int chalf = lane >> 4;
    const int qrow = wid * 16 + rsel;

    float O[8][4];
    #pragma unroll
    for (int j = 0; j < 8; j++)
        #pragma unroll
        for (int e = 0; e < 4; e++) O[j][e] = 0.f;
    float m0r = -1e30f, m1r = -1e30f, l0 = 0.f, l1 = 0.f;
    const int g = lane >> 2, q2 = (lane & 3) * 2;
    const int qr0 = wid * 16 + g;

    for (int t = 0; t < 32; t++) {
        if (t < 31) { attn_issue(smb, kh, kl, vh, t + 1, (t + 1) & 1, tid); CP_WAIT1(); }
        else CP_WAIT0();
        __syncthreads();
        uint32_t kb = smb + AT_KV + (t & 1) * 24576;

        float s[8][4];
        #pragma unroll
        for (int j = 0; j < 8; j++)
            #pragma unroll
            for (int e = 0; e < 4; e++) s[j][e] = 0.f;

        #pragma unroll
        for (int ks = 0; ks < 4; ks++) {
            int sseg = 2 * ks + chalf;
            // Q fragments loaded per-ks (hi+lo) to keep live regs < 128 (no spills @ 2 CTAs/SM)
            uint32_t qfh[4], qfl[4];
            uint32_t qoff = qrow * 128 + ((sseg ^ (qrow & 7)) << 4);
            ldsm4(qfh, smb + AT_QH + qoff);
            ldsm4(qfl, smb + AT_QL + qoff);
            #pragma unroll
            for (int njp = 0; njp < 4; njp++) {
                int row = njp * 16 + rsel;
                uint32_t off = row * 128 + ((sseg ^ (row & 7)) << 4);
                uint32_t kbh[4], kbl[4];
                ldsm4(kbh, kb + off);
                ldsm4(kbl, kb + 8192 + off);
                hmma(s[2*njp],   qfh, kbh[0], kbh[2]);
                hmma(s[2*njp+1], qfh, kbh[1], kbh[3]);
                hmma(s[2*njp],   qfh, kbl[0], kbl[2]);
                hmma(s[2*njp+1], qfh, kbl[1], kbl[3]);
                hmma(s[2*njp],   qfl, kbh[0], kbh[2]);
                hmma(s[2*njp+1], qfl, kbh[1], kbh[3]);
            }
        }

        // bias + in-register online softmax (rows qr0, qr0+8)
        const float* bp0 = biasS + t * 64 + q2 + 127 - qr0;
        const float* bp1 = bp0 - 8;
        float mx0 = m0r, mx1 = m1r;
        #pragma unroll
        for (int nj = 0; nj < 8; nj++) {
            s[nj][0] += bp0[nj * 8];     s[nj][1] += bp0[nj * 8 + 1];
            s[nj][2] += bp1[nj * 8];     s[nj][3] += bp1[nj * 8 + 1];
            mx0 = fmaxf(mx0, fmaxf(s[nj][0], s[nj][1]));
            mx1 = fmaxf(mx1, fmaxf(s[nj][2], s[nj][3]));
        }
        mx0 = fmaxf(mx0, __shfl_xor_sync(0xffffffffu, mx0, 1));
        mx0 = fmaxf(mx0, __shfl_xor_sync(0xffffffffu, mx0, 2));
        mx1 = fmaxf(mx1, __shfl_xor_sync(0xffffffffu, mx1, 1));
        mx1 = fmaxf(mx1, __shfl_xor_sync(0xffffffffu, mx1, 2));
        float c0 = exp2f((m0r - mx0) * LOG2E);
        float c1 = exp2f((m1r - mx1) * LOG2E);
        m0r = mx0; m1r = mx1;
        float sum0 = 0.f, sum1 = 0.f;
        #pragma unroll
        for (int nj = 0; nj < 8; nj++) {
            s[nj][0] = exp2f((s[nj][0] - mx0) * LOG2E);
            s[nj][1] = exp2f((s[nj][1] - mx0) * LOG2E);
            s[nj][2] = exp2f((s[nj][2] - mx1) * LOG2E);
            s[nj][3] = exp2f((s[nj][3] - mx1) * LOG2E);
            sum0 += s[nj][0] + s[nj][1];
            sum1 += s[nj][2] + s[nj][3];
        }
        sum0 += __shfl_xor_sync(0xffffffffu, sum0, 1);
        sum0 += __shfl_xor_sync(0xffffffffu, sum0, 2);
        sum1 += __shfl_xor_sync(0xffffffffu, sum1, 1);
        sum1 += __shfl_xor_sync(0xffffffffu, sum1, 2);
        l0 = l0 * c0 + sum0;
        l1 = l1 * c1 + sum1;
        #pragma unroll
        for (int nd = 0; nd < 8; nd++) {
            O[nd][0] *= c0; O[nd][1] *= c0; O[nd][2] *= c1; O[nd][3] *= c1;
        }

        // P acc -> A-fragments, then PV
        #pragma unroll
        for (int kv = 0; kv < 4; kv++) {
            uint32_t pf[4];
            pf[0] = packh2(s[2*kv][0],   s[2*kv][1]);
            pf[1] = packh2(s[2*kv][2],   s[2*kv][3]);
            pf[2] = packh2(s[2*kv+1][0], s[2*kv+1][1]);
            pf[3] = packh2(s[2*kv+1][2], s[2*kv+1][3]);
            int krow = kv * 16 + rsel;
            #pragma unroll
            for (int ndp = 0; ndp < 4; ndp++) {
                int seg = 2 * ndp + chalf;
                uint32_t off = krow * 128 + ((seg ^ (krow & 7)) << 4);
                uint32_t vb[4];
                ldsm4t(vb, kb + 16384 + off);
                hmma(O[2*ndp],   pf, vb[0], vb[1]);
                hmma(O[2*ndp+1], pf, vb[2], vb[3]);
            }
        }
        __syncthreads();
    }

    // epilogue: ctx hi-only row-major [b*S+q][h*64+d]
    float inv0 = 1.0f / l0, inv1 = 1.0f / l1;
    #pragma unroll
    for (int rr = 0; rr < 2; rr++) {
        int q = q0 + wid * 16 + g + rr * 8;
        float inv = rr ? inv1 : inv0;
        size_t base = ((size_t)(b * SEQ + q)) * DM + h * DKV + q2;
        #pragma unroll
        for (int nd = 0; nd < 8; nd++) {
            uint32_t ph = packh2(O[nd][rr * 2] * inv, O[nd][rr * 2 + 1] * inv);
            *(uint32_t*)(g_ch + base + nd * 8) = ph;
        }
    }
}

// ---------------------------------------------------------------------------
extern "C" void kernel_launch(void* const* d_in, const int* in_sizes, int n_in,
                              void* d_out, int out_size)
{
    const float* x   = (const float*)d_in[0];
    const float* wq  = (const float*)d_in[1];
    const float* wk  = (const float*)d_in[2];
    const float* wv  = (const float*)d_in[3];
    const float* wo  = (const float*)d_in[4];
    const float* rel = (const float*)d_in[5];
    float* out = (float*)d_out;

    cudaFuncSetAttribute(qkv_gemm, cudaFuncAttributeMaxDynamicSharedMemorySize, G_SMEM);
    cudaFuncSetAttribute(out_gemm, cudaFuncAttributeMaxDynamicSharedMemorySize, G3_SMEM);
    cudaFuncSetAttribute(attn_mma, cudaFuncAttributeMaxDynamicSharedMemorySize, AT_SMEM);

    // launch order chosen so attn_mma is the 5th launch (ncu -s 5 capture)
    split_x_kernel<<<MTOT*DM/1024, 256>>>(x);
    dim3 wg(32, 32, 2), wb(32, 8);
    wsplit2_kernel<<<wg, wb>>>(wq, wk, 0);
    wsplit2_kernel<<<wg, wb>>>(wv, wo, 2);
    qkv_gemm<<<dim3(DM/128, MTOT/128, 3), 256, G_SMEM>>>();
    attn_mma<<<dim3(SEQ/128, NH, BATCH), 256, AT_SMEM>>>(rel);
    out_gemm<<<dim3(DM/128, MTOT/128), 256, G3_SMEM>>>(out);
}

// round 12
// speedup vs baseline: 4.4099x; 1.0029x over previous
#include <cuda_runtime.h>
#include <cuda_fp16.h>
#include <stdint.h>
#include <math.h>

#define SEQ   2048
#define BATCH 2
#define NH    16
#define DKV   64
#define DM    1024
#define MTOT  (BATCH*SEQ)
#define LOG2E 1.44269504f

// ---- static device scratch (no allocs) ----
__device__ __align__(16) __half g_xh[MTOT*DM], g_xl[MTOT*DM];
__device__ __align__(16) __half g_wth[4][DM*DM], g_wtl[4][DM*DM];
__device__ __align__(16) __half g_qh[BATCH*NH*SEQ*DKV], g_ql[BATCH*NH*SEQ*DKV];
__device__ __align__(16) __half g_kh[BATCH*NH*SEQ*DKV], g_kl[BATCH*NH*SEQ*DKV];
__device__ __align__(16) __half g_vh[BATCH*NH*SEQ*DKV];
__device__ __align__(16) __half g_ch[MTOT*DM];

// ---- helpers ----
__device__ __forceinline__ uint32_t smem_u32(const void* p) {
    uint32_t a;
    asm("{ .reg .u64 t; cvta.to.shared.u64 t, %1; cvt.u32.u64 %0, t; }" : "=r"(a) : "l"(p));
    return a;
}
__device__ __forceinline__ void hmma(float* d, const uint32_t* a, uint32_t b0, uint32_t b1) {
    asm volatile("mma.sync.aligned.m16n8k16.row.col.f32.f16.f16.f32 "
        "{%0,%1,%2,%3}, {%4,%5,%6,%7}, {%8,%9}, {%0,%1,%2,%3};"
        : "+f"(d[0]), "+f"(d[1]), "+f"(d[2]), "+f"(d[3])
        : "r"(a[0]), "r"(a[1]), "r"(a[2]), "r"(a[3]), "r"(b0), "r"(b1));
}
__device__ __forceinline__ void ldsm4(uint32_t* r, uint32_t addr) {
    asm volatile("ldmatrix.sync.aligned.m8n8.x4.shared.b16 {%0,%1,%2,%3}, [%4];"
        : "=r"(r[0]), "=r"(r[1]), "=r"(r[2]), "=r"(r[3]) : "r"(addr));
}
__device__ __forceinline__ void ldsm4t(uint32_t* r, uint32_t addr) {
    asm volatile("ldmatrix.sync.aligned.m8n8.x4.trans.shared.b16 {%0,%1,%2,%3}, [%4];"
        : "=r"(r[0]), "=r"(r[1]), "=r"(r[2]), "=r"(r[3]) : "r"(addr));
}
__device__ __forceinline__ void cpa(uint32_t dst, const void* src) {
    asm volatile("cp.async.cg.shared.global [%0], [%1], 16;" :: "r"(dst), "l"(src));
}
#define CP_COMMIT() asm volatile("cp.async.commit_group;" ::: "memory")
#define CP_WAIT1()  asm volatile("cp.async.wait_group 1;" ::: "memory")
#define CP_WAIT0()  asm volatile("cp.async.wait_group 0;" ::: "memory")

__device__ __forceinline__ void split2(float v, __half& hi, __half& lo) {
    hi = __float2half_rn(v);
    lo = __float2half_rn(v - __half2float(hi));
}
__device__ __forceinline__ uint32_t packh2(float a, float b) {
    __half2 h = __floats2half2_rn(a, b);
    return *(uint32_t*)&h;
}

// ---- prep ----
__global__ __launch_bounds__(256) void split_x_kernel(const float* __restrict__ x) {
    int i = (blockIdx.x * 256 + threadIdx.x) * 4;
    float4 v = *(const float4*)(x + i);
    __half h0,h1,h2,h3,l0,l1,l2,l3;
    split2(v.x,h0,l0); split2(v.y,h1,l1); split2(v.z,h2,l2); split2(v.w,h3,l3);
    __half2 hh[2] = { __halves2half2(h0,h1), __halves2half2(h2,h3) };
    __half2 ll[2] = { __halves2half2(l0,l1), __halves2half2(l2,l3) };
    *(uint2*)(g_xh + i) = *(uint2*)hh;
    *(uint2*)(g_xl + i) = *(uint2*)ll;
}
__global__ __launch_bounds__(256) void wsplit2_kernel(const float* __restrict__ Wa,
                                                      const float* __restrict__ Wb, int widx0) {
    __shared__ float t[32][33];
    const float* W = blockIdx.z ? Wb : Wa;
    int widx = widx0 + blockIdx.z;
    int n0 = blockIdx.x * 32, k0 = blockIdx.y * 32;
    int tx = threadIdx.x, ty = threadIdx.y;
    #pragma unroll
    for (int i = 0; i < 32; i += 8)
        t[ty + i][tx] = W[(size_t)(k0 + ty + i) * DM + n0 + tx];
    __syncthreads();
    #pragma unroll
    for (int i = 0; i < 32; i += 8) {
        int n = n0 + ty + i, k = k0 + tx;
        __half hi, lo; split2(t[tx][ty + i], hi, lo);
        g_wth[widx][(size_t)n * DM + k] = hi;
        g_wtl[widx][(size_t)n * DM + k] = lo;
    }
}

// ---- split-fp16 MMA GEMM mainloops (K-chunk 32, 3-stage, single barrier/stage) ----
#define GS_BUF  32768
#define G_SMEM  (3*GS_BUF)
#define GS3_BUF 24576
#define G3_SMEM (3*GS3_BUF)
#define NCH     32

__device__ __forceinline__ void g_issue(uint32_t smb, const __half* const* mats,
                                        int c, int tid) {
    if (c < NCH) {
        uint32_t bufb = smb + (c % 3) * GS_BUF;
        #pragma unroll
        for (int i = 0; i < 8; i++) {
            int u = tid + i * 256;
            int mat = u >> 9, rem = u & 511, row = rem >> 2, seg = rem & 3;
            const void* src = mats[mat] + (size_t)row * DM + c * 32 + seg * 8;
            uint32_t dst = bufb + mat * 8192 + row * 64 + ((seg ^ ((row >> 1) & 3)) << 4);
            cpa(dst, src);
        }
    }
    CP_COMMIT();
}

// 3-term: acc += Ah*Bh + Ah*Bl + Al*Bh    (mats = {Ah, Al, Bh, Bl})
__device__ __forceinline__ void g_mainloop(uint32_t smb, const __half* const* mats,
                                           float acc[2][8][4], int tid) {
    const int lane = tid & 31, wid = tid >> 5;
    const int wm = wid >> 1, wn = wid & 1;
    const int rsel = (lane & 7) + ((lane >> 3) & 1) * 8;
    const int chalf = lane >> 4;

    g_issue(smb, mats, 0, tid);
    g_issue(smb, mats, 1, tid);
    for (int c = 0; c < NCH; c++) {
        CP_WAIT1();
        __syncthreads();          // chunk c visible; all warps done with slot (c+2)%3's old data
        g_issue(smb, mats, c + 2, tid);
        uint32_t ab = smb + (c % 3) * GS_BUF;
        #pragma unroll
        for (int ks = 0; ks < 2; ks++) {
            int sseg = 2 * ks + chalf;
            uint32_t ah[2][4], al_[2][4];
            #pragma unroll
            for (int mi = 0; mi < 2; mi++) {
                int row = wm * 32 + mi * 16 + rsel;
                uint32_t off = row * 64 + ((sseg ^ ((row >> 1) & 3)) << 4);
                ldsm4(ah[mi], ab + off);
                ldsm4(al_[mi], ab + 8192 + off);
            }
            #pragma unroll
            for (int njp = 0; njp < 4; njp++) {
                int row = wn * 64 + njp * 16 + rsel;
                uint32_t off = row * 64 + ((sseg ^ ((row >> 1) & 3)) << 4);
                uint32_t bh_[4], bl_[4];
                ldsm4(bh_, ab + 16384 + off);
                ldsm4(bl_, ab + 24576 + off);
                #pragma unroll
                for (int mi = 0; mi < 2; mi++) {
                    hmma(acc[mi][2*njp],   ah[mi],  bh_[0], bh_[2]);
                    hmma(acc[mi][2*njp+1], ah[mi],  bh_[1], bh_[3]);
                    hmma(acc[mi][2*njp],   ah[mi],  bl_[0], bl_[2]);
                    hmma(acc[mi][2*njp+1], ah[mi],  bl_[1], bl_[3]);
                    hmma(acc[mi][2*njp],   al_[mi], bh_[0], bh_[2]);
                    hmma(acc[mi][2*njp+1], al_[mi], bh_[1], bh_[3]);
                }
            }
        }
    }
}

__device__ __forceinline__ void g_issue3(uint32_t smb, const __half* const* mats,
                                         int c, int tid) {
    if (c < NCH) {
        uint32_t bufb = smb + (c % 3) * GS3_BUF;
        #pragma unroll
        for (int i = 0; i < 6; i++) {
            int u = tid + i * 256;
            int mat = u >> 9, rem = u & 511, row = rem >> 2, seg = rem & 3;
            const void* src = mats[mat] + (size_t)row * DM + c * 32 + seg * 8;
            uint32_t dst = bufb + mat * 8192 + row * 64 + ((seg ^ ((row >> 1) & 3)) << 4);
            cpa(dst, src);
        }
    }
    CP_COMMIT();
}

// 2-term: acc += A*Bh + A*Bl    (mats = {A, Bh, Bl})
__device__ __forceinline__ void g_mainloop3(uint32_t smb, const __half* const* mats,
                                            float acc[2][8][4], int tid) {
    const int lane = tid & 31, wid = tid >> 5;
    const int wm = wid >> 1, wn = wid & 1;
    const int rsel = (lane & 7) + ((lane >> 3) & 1) * 8;
    const int chalf = lane >> 4;

    g_issue3(smb, mats, 0, tid);
    g_issue3(smb, mats, 1, tid);
    for (int c = 0; c < NCH; c++) {
        CP_WAIT1();
        __syncthreads();
        g_issue3(smb, mats, c + 2, tid);
        uint32_t ab = smb + (c % 3) * GS3_BUF;
        #pragma unroll
        for (int ks = 0; ks < 2; ks++) {
            int sseg = 2 * ks + chalf;
            uint32_t ah[2][4];
            #pragma unroll
            for (int mi = 0; mi < 2; mi++) {
                int row = wm * 32 + mi * 16 + rsel;
                uint32_t off = row * 64 + ((sseg ^ ((row >> 1) & 3)) << 4);
                ldsm4(ah[mi], ab + off);
            }
            #pragma unroll
            for (int njp = 0; njp < 4; njp++) {
                int row = wn * 64 + njp * 16 + rsel;
                uint32_t off = row * 64 + ((sseg ^ ((row >> 1) & 3)) << 4);
                uint32_t bh_[4], bl_[4];
                ldsm4(bh_, ab + 8192 + off);
                ldsm4(bl_, ab + 16384 + off);
                #pragma unroll
                for (int mi = 0; mi < 2; mi++) {
                    hmma(acc[mi][2*njp],   ah[mi], bh_[0], bh_[2]);
                    hmma(acc[mi][2*njp+1], ah[mi], bh_[1], bh_[3]);
                    hmma(acc[mi][2*njp],   ah[mi], bl_[0], bl_[2]);
                    hmma(acc[mi][2*njp+1], ah[mi], bl_[1], bl_[3]);
                }
            }
        }
    }
}

// Fused QKV projection: z = 0(Q, hi/lo), 1(K, hi/lo), 2(V, hi-only)
__global__ __launch_bounds__(256, 2) void qkv_gemm() {
    extern __shared__ char smg[];
    uint32_t smb = smem_u32(smg);
    const int tid = threadIdx.x, lane = tid & 31, wid = tid >> 5;
    const int m0 = blockIdx.y * 128, n0 = blockIdx.x * 128, z = blockIdx.z;
    const int wm = wid >> 1, wn = wid & 1;

    const __half* mats[4] = { g_xh + (size_t)m0 * DM, g_xl + (size_t)m0 * DM,
                              g_wth[z] + (size_t)n0 * DM, g_wtl[z] + (size_t)n0 * DM };
    float acc[2][8][4];
    #pragma unroll
    for (int i = 0; i < 2; i++)
        #pragma unroll
        for (int j = 0; j < 8; j++)
            #pragma unroll
            for (int e = 0; e < 4; e++) acc[i][j][e] = 0.f;

    g_mainloop(smb, mats, acc, tid);

    __half* Oh = (z == 0) ? g_qh : (z == 1) ? g_kh : g_vh;
    __half* Ol = (z == 0) ? g_ql : g_kl;
    const int g = lane >> 2, q2 = (lane & 3) * 2;
    #pragma unroll
    for (int mi = 0; mi < 2; mi++)
        #pragma unroll
        for (int rr = 0; rr < 2; rr++) {
            int m = m0 + wm * 32 + mi * 16 + g + rr * 8;
            int bb = m >> 11, ss = m & (SEQ - 1);
            #pragma unroll
            for (int nj = 0; nj < 8; nj++) {
                float v0 = acc[mi][nj][rr * 2], v1 = acc[mi][nj][rr * 2 + 1];
                int n = n0 + wn * 64 + nj * 8 + q2;
                int hh = n >> 6, dd = n & 63;
                size_t off = (((size_t)(bb * NH + hh)) * SEQ + ss) * DKV + dd;
                __half h0, h1, l0, l1;
                split2(v0, h0, l0); split2(v1, h1, l1);
                __half2 ph = __halves2half2(h0, h1);
                *(uint32_t*)(Oh + off) = *(uint32_t*)&ph;
                if (z < 2) {
                    __half2 pl = __halves2half2(l0, l1);
                    *(uint32_t*)(Ol + off) = *(uint32_t*)&pl;
                }
            }
        }
}

// Output GEMM: out = ctx_hi @ wo, 2-term (wo hi+lo), fp32 row-major
__global__ __launch_bounds__(256, 2) void out_gemm(float* __restrict__ Cf) {
    extern __shared__ char smg[];
    uint32_t smb = smem_u32(smg);
    const int tid = threadIdx.x, lane = tid & 31, wid = tid >> 5;
    const int m0 = blockIdx.y * 128, n0 = blockIdx.x * 128;
    const int wm = wid >> 1, wn = wid & 1;

    const __half* mats[3] = { g_ch + (size_t)m0 * DM,
                              g_wth[3] + (size_t)n0 * DM, g_wtl[3] + (size_t)n0 * DM };
    float acc[2][8][4];
    #pragma unroll
    for (int i = 0; i < 2; i++)
        #pragma unroll
        for (int j = 0; j < 8; j++)
            #pragma unroll
            for (int e = 0; e < 4; e++) acc[i][j][e] = 0.f;

    g_mainloop3(smb, mats, acc, tid);

    const int g = lane >> 2, q2 = (lane & 3) * 2;
    #pragma unroll
    for (int mi = 0; mi < 2; mi++)
        #pragma unroll
        for (int rr = 0; rr < 2; rr++) {
            int m = m0 + wm * 32 + mi * 16 + g + rr * 8;
            #pragma unroll
            for (int nj = 0; nj < 8; nj++) {
                int n = n0 + wn * 64 + nj * 8 + q2;
                *(float2*)(Cf + (size_t)m * DM + n) =
                    make_float2(acc[mi][nj][rr * 2], acc[mi][nj][rr * 2 + 1]);
            }
        }
}

// ---- FA2-style mma.sync flash attention ----
#define AT_QH 0
#define AT_QL 16384
#define AT_KV 32768            /* 2 bufs x 24576 (Kh 8K | Kl 8K | V 8K) */
#define AT_BI 81920
#define AT_SMEM (81920 + 2176*4)

__device__ __forceinline__ void attn_issue(uint32_t smb, const __half* kh, const __half* kl,
                                           const __half* vh, int t, int buf, int tid) {
    #pragma unroll
    for (int i = 0; i < 6; i++) {
        int u = tid + i * 256;
        int mat = u >> 9, rem = u & 511, row = rem >> 3, seg = rem & 7;
        const __half* base = (mat == 0) ? kh : (mat == 1) ? kl : vh;
        const void* src = base + (size_t)(t * 64 + row) * DKV + seg * 8;
        uint32_t dst = smb + AT_KV + buf * 24576 + mat * 8192 + row * 128 + ((seg ^ (row & 7)) << 4);
        cpa(dst, src);
    }
    CP_COMMIT();
}

__global__ __launch_bounds__(256, 2) void attn_mma(const float* __restrict__ rel_emb)
{
    extern __shared__ char smn[];
    uint32_t smb = smem_u32(smn);
    const int tid = threadIdx.x, lane = tid & 31, wid = tid >> 5;
    const int b = blockIdx.z, h = blockIdx.y, q0 = blockIdx.x * 128;
    const size_t hoff = ((size_t)(b * NH + h)) * SEQ * DKV;
    const __half* kh = g_kh + hoff;
    const __half* kl = g_kl + hoff;
    const __half* vh = g_vh + hoff;

    attn_issue(smb, kh, kl, vh, 0, 0, tid);

    // Q staging (hi/lo), swizzled (128B rows)
    #pragma unroll
    for (int i = 0; i < 8; i++) {
        int u = tid + i * 256;
        int mat = u >> 10, rem = u & 1023, row = rem >> 3, seg = rem & 7;
        const uint4* src = (const uint4*)(((mat == 0) ? g_qh : g_ql) + hoff
                             + (size_t)(q0 + row) * DKV + seg * 8);
        *(uint4*)(smn + mat * 16384 + row * 128 + ((seg ^ (row & 7)) << 4)) = *src;
    }
    // bias table (exact reference bucket math)
    float* biasS = (float*)(smn + AT_BI);
    for (int j = tid; j < 2175; j += 256) {
        int rel = j - (q0 + 127);
        int n = -rel, ret = 0;
        if (n < 0) { ret = 16; n = -n; }
        int bkt;
        if (n < 8) bkt = n;
        else {
            float t = logf((float)n * 0.125f) / 2.7725887222397812f * 8.0f;
            int v = 8 + (int)t;
            bkt = v < 15 ? v : 15;
        }
        biasS[j] = __ldg(&rel_emb[(ret + bkt) * NH + h]);
    }
    __syncthreads();

    const int rsel = (lane & 7) + ((lane >> 3) & 1) * 8;
    const int chalf = lane >> 4;
    const int qrow = wid * 16 + rsel;

    float O[8][4];
    #pragma unroll
    for (int j = 0; j < 8; j++)
        #pragma unroll
        for (int e = 0; e < 4; e++) O[j][e] = 0.f;
    float m0r = -1e30f, m1r = -1e30f, l0 = 0.f, l1 = 0.f;
    const int g = lane >> 2, q2 = (lane & 3) * 2;
    const int qr0 = wid * 16 + g;

    for (int t = 0; t < 32; t++) {
        CP_WAIT0();
        __syncthreads();          // tile t visible; all warps done reading the other buffer
        if (t < 31) attn_issue(smb, kh, kl, vh, t + 1, (t + 1) & 1, tid);
        uint32_t kb = smb + AT_KV + (t & 1) * 24576;

        float s[8][4];
        #pragma unroll
        for (int j = 0; j < 8; j++)
            #pragma unroll
            for (int e = 0; e < 4; e++) s[j][e] = 0.f;

        #pragma unroll
        for (int ks = 0; ks < 4; ks++) {
            int sseg = 2 * ks + chalf;
            uint32_t qfh[4], qfl[4];
            uint32_t qoff = qrow * 128 + ((sseg ^ (qrow & 7)) << 4);
            ldsm4(qfh, smb + AT_QH + qoff);
            ldsm4(qfl, smb + AT_QL + qoff);
            #pragma unroll
            for (int njp = 0; njp < 4; njp++) {
                int row = njp * 16 + rsel;
                uint32_t off = row * 128 + ((sseg ^ (row & 7)) << 4);
                uint32_t kbh[4], kbl[4];
                ldsm4(kbh, kb + off);
                ldsm4(kbl, kb + 8192 + off);
                hmma(s[2*njp],   qfh, kbh[0], kbh[2]);
                hmma(s[2*njp+1], qfh, kbh[1], kbh[3]);
                hmma(s[2*njp],   qfh, kbl[0], kbl[2]);
                hmma(s[2*njp+1], qfh, kbl[1], kbl[3]);
                hmma(s[2*njp],   qfl, kbh[0], kbh[2]);
                hmma(s[2*njp+1], qfl, kbh[1], kbh[3]);
            }
        }

        // bias + in-register online softmax (rows qr0, qr0+8)
        const float* bp0 = biasS + t * 64 + q2 + 127 - qr0;
        const float* bp1 = bp0 - 8;
        float mx0 = m0r, mx1 = m1r;
        #pragma unroll
        for (int nj = 0; nj < 8; nj++) {
            s[nj][0] += bp0[nj * 8];     s[nj][1] += bp0[nj * 8 + 1];
            s[nj][2] += bp1[nj * 8];     s[nj][3] += bp1[nj * 8 + 1];
            mx0 = fmaxf(mx0, fmaxf(s[nj][0], s[nj][1]));
            mx1 = fmaxf(mx1, fmaxf(s[nj][2], s[nj][3]));
        }
        mx0 = fmaxf(mx0, __shfl_xor_sync(0xffffffffu, mx0, 1));
        mx0 = fmaxf(mx0, __shfl_xor_sync(0xffffffffu, mx0, 2));
        mx1 = fmaxf(mx1, __shfl_xor_sync(0xffffffffu, mx1, 1));
        mx1 = fmaxf(mx1, __shfl_xor_sync(0xffffffffu, mx1, 2));
        float c0 = exp2f((m0r - mx0) * LOG2E);
        float c1 = exp2f((m1r - mx1) * LOG2E);
        m0r = mx0; m1r = mx1;
        float sum0 = 0.f, sum1 = 0.f;
        #pragma unroll
        for (int nj = 0; nj < 8; nj++) {
            s[nj][0] = exp2f((s[nj][0] - mx0) * LOG2E);
            s[nj][1] = exp2f((s[nj][1] - mx0) * LOG2E);
            s[nj][2] = exp2f((s[nj][2] - mx1) * LOG2E);
            s[nj][3] = exp2f((s[nj][3] - mx1) * LOG2E);
            sum0 += s[nj][0] + s[nj][1];
            sum1 += s[nj][2] + s[nj][3];
        }
        sum0 += __shfl_xor_sync(0xffffffffu, sum0, 1);
        sum0 += __shfl_xor_sync(0xffffffffu, sum0, 2);
        sum1 += __shfl_xor_sync(0xffffffffu, sum1, 1);
        sum1 += __shfl_xor_sync(0xffffffffu, sum1, 2);
        l0 = l0 * c0 + sum0;
        l1 = l1 * c1 + sum1;
        #pragma unroll
        for (int nd = 0; nd < 8; nd++) {
            O[nd][0] *= c0; O[nd][1] *= c0; O[nd][2] *= c1; O[nd][3] *= c1;
        }

        // P acc -> A-fragments, then PV
        #pragma unroll
        for (int kv = 0; kv < 4; kv++) {
            uint32_t pf[4];
            pf[0] = packh2(s[2*kv][0],   s[2*kv][1]);
            pf[1] = packh2(s[2*kv][2],   s[2*kv][3]);
            pf[2] = packh2(s[2*kv+1][0], s[2*kv+1][1]);
            pf[3] = packh2(s[2*kv+1][2], s[2*kv+1][3]);
            int krow = kv * 16 + rsel;
            #pragma unroll
            for (int ndp = 0; ndp < 4; ndp++) {
                int seg = 2 * ndp + chalf;
                uint32_t off = krow * 128 + ((seg ^ (krow & 7)) << 4);
                uint32_t vb[4];
                ldsm4t(vb, kb + 16384 + off);
                hmma(O[2*ndp],   pf, vb[0], vb[1]);
                hmma(O[2*ndp+1], pf, vb[2], vb[3]);
            }
        }
    }

    // epilogue: ctx hi-only row-major [b*S+q][h*64+d]
    float inv0 = 1.0f / l0, inv1 = 1.0f / l1;
    #pragma unroll
    for (int rr = 0; rr < 2; rr++) {
        int q = q0 + wid * 16 + g + rr * 8;
        float inv = rr ? inv1 : inv0;
        size_t base = ((size_t)(b * SEQ + q)) * DM + h * DKV + q2;
        #pragma unroll
        for (int nd = 0; nd < 8; nd++) {
            uint32_t ph = packh2(O[nd][rr * 2] * inv, O[nd][rr * 2 + 1] * inv);
            *(uint32_t*)(g_ch + base + nd * 8) = ph;
        }
    }
}

// ---------------------------------------------------------------------------
extern "C" void kernel_launch(void* const* d_in, const int* in_sizes, int n_in,
                              void* d_out, int out_size)
{
    const float* x   = (const float*)d_in[0];
    const float* wq  = (const float*)d_in[1];
    const float* wk  = (const float*)d_in[2];
    const float* wv  = (const float*)d_in[3];
    const float* wo  = (const float*)d_in[4];
    const float* rel = (const float*)d_in[5];
    float* out = (float*)d_out;

    cudaFuncSetAttribute(qkv_gemm, cudaFuncAttributeMaxDynamicSharedMemorySize, G_SMEM);
    cudaFuncSetAttribute(out_gemm, cudaFuncAttributeMaxDynamicSharedMemorySize, G3_SMEM);
    cudaFuncSetAttribute(attn_mma, cudaFuncAttributeMaxDynamicSharedMemorySize, AT_SMEM);

    split_x_kernel<<<MTOT*DM/1024, 256>>>(x);
    dim3 wg(32, 32, 2), wb(32, 8);
    wsplit2_kernel<<<wg, wb>>>(wq, wk, 0);
    wsplit2_kernel<<<wg, wb>>>(wv, wo, 2);
    qkv_gemm<<<dim3(DM/128, MTOT/128, 3), 256, G_SMEM>>>();
    attn_mma<<<dim3(SEQ/128, NH, BATCH), 256, AT_SMEM>>>(rel);
    out_gemm<<<dim3(DM/128, MTOT/128), 256, G3_SMEM>>>(out);
}